// round 1
// baseline (speedup 1.0000x reference)
#include <cuda_runtime.h>

#define BSZ 2
#define TSEQ 1024
#define DMODEL 1024
#define NH 8
#define HD 128
#define BT (BSZ * TSEQ)   // 2048

// -------- scratch (no cudaMalloc allowed) --------
__device__ float g_Q[NH * BSZ * TSEQ * DMODEL];   // 67 MB
__device__ float g_K[NH * BSZ * TSEQ * DMODEL];   // 67 MB
__device__ float g_V[BSZ * TSEQ * DMODEL];        // 8 MB
__device__ float g_head[BSZ * TSEQ * DMODEL];     // 8 MB

// ============================================================
// C[m,n] = sum_k A[m,k] * B[n,k]   (A MxK row-major, B NxK row-major)
// grid: (N/128, M/128, batch); 256 threads; 8x8 per thread, BK=16
// ============================================================
__global__ __launch_bounds__(256) void sgemm_abt(
    const float* __restrict__ A, const float* __restrict__ B, float* __restrict__ C,
    int K, int lda, int ldb, int ldc,
    long sA, long sB, long sC)
{
    __shared__ float As[16][132];
    __shared__ float Bs[16][132];

    const float* Ab = A + (size_t)blockIdx.z * sA + (size_t)blockIdx.y * 128 * lda;
    const float* Bb = B + (size_t)blockIdx.z * sB + (size_t)blockIdx.x * 128 * ldb;
    float* Cb = C + (size_t)blockIdx.z * sC + (size_t)blockIdx.y * 128 * ldc + blockIdx.x * 128;

    int tid = threadIdx.x;
    int tx = tid & 15, ty = tid >> 4;
    int lrow = tid >> 2;
    int lq = (tid & 3) * 4;

    float acc[8][8] = {};

    for (int k0 = 0; k0 < K; k0 += 16) {
#pragma unroll
        for (int half = 0; half < 2; half++) {
            int row = lrow + half * 64;
            float4 av = *(const float4*)(Ab + (size_t)row * lda + k0 + lq);
            float4 bv = *(const float4*)(Bb + (size_t)row * ldb + k0 + lq);
            As[lq + 0][row] = av.x; As[lq + 1][row] = av.y;
            As[lq + 2][row] = av.z; As[lq + 3][row] = av.w;
            Bs[lq + 0][row] = bv.x; Bs[lq + 1][row] = bv.y;
            Bs[lq + 2][row] = bv.z; Bs[lq + 3][row] = bv.w;
        }
        __syncthreads();
#pragma unroll
        for (int k = 0; k < 16; k++) {
            float a[8], b8[8];
            *(float4*)(a)     = *(float4*)&As[k][ty * 8];
            *(float4*)(a + 4) = *(float4*)&As[k][ty * 8 + 4];
            *(float4*)(b8)     = *(float4*)&Bs[k][tx * 8];
            *(float4*)(b8 + 4) = *(float4*)&Bs[k][tx * 8 + 4];
#pragma unroll
            for (int i = 0; i < 8; i++)
#pragma unroll
                for (int j = 0; j < 8; j++)
                    acc[i][j] = fmaf(a[i], b8[j], acc[i][j]);
        }
        __syncthreads();
    }

#pragma unroll
    for (int i = 0; i < 8; i++) {
        float4 v0 = make_float4(acc[i][0], acc[i][1], acc[i][2], acc[i][3]);
        float4 v1 = make_float4(acc[i][4], acc[i][5], acc[i][6], acc[i][7]);
        float* crow = Cb + (size_t)(ty * 8 + i) * ldc + tx * 8;
        *(float4*)(crow)     = v0;
        *(float4*)(crow + 4) = v1;
    }
}

// ============================================================
// head_gemm: per (b,h): C[t, e] = sum_s attn[b,h,t,s] * V[b, s, h*128+e]
// grid: (1, TSEQ/128, BSZ*NH); 256 threads; 8x8 per thread, BK=16
// ============================================================
__global__ __launch_bounds__(256) void head_gemm(
    const float* __restrict__ attn, const float* __restrict__ V, float* __restrict__ Ch)
{
    int z = blockIdx.z, b = z >> 3, h = z & 7;
    const float* Ab = attn + (size_t)z * TSEQ * TSEQ + (size_t)blockIdx.y * 128 * TSEQ;
    const float* Bb = V + (size_t)b * TSEQ * DMODEL + h * HD;
    float* Cb = g_head + (size_t)b * TSEQ * DMODEL + (size_t)blockIdx.y * 128 * DMODEL + h * HD;
    (void)Ch;

    __shared__ float As[16][132];
    __shared__ float Bs[16][128];

    int tid = threadIdx.x;
    int tx = tid & 15, ty = tid >> 4;
    int lrow = tid >> 2;
    int lq = (tid & 3) * 4;

    float acc[8][8] = {};

    for (int k0 = 0; k0 < TSEQ; k0 += 16) {
#pragma unroll
        for (int half = 0; half < 2; half++) {
            int row = lrow + half * 64;
            float4 av = *(const float4*)(Ab + (size_t)row * TSEQ + k0 + lq);
            As[lq + 0][row] = av.x; As[lq + 1][row] = av.y;
            As[lq + 2][row] = av.z; As[lq + 3][row] = av.w;
        }
#pragma unroll
        for (int it = 0; it < 2; it++) {
            int f = tid + it * 256;
            int kr = f >> 5, c4 = f & 31;
            *(float4*)(&Bs[kr][c4 * 4]) =
                *(const float4*)(Bb + (size_t)(k0 + kr) * DMODEL + c4 * 4);
        }
        __syncthreads();
#pragma unroll
        for (int k = 0; k < 16; k++) {
            float a[8], b8[8];
            *(float4*)(a)     = *(float4*)&As[k][ty * 8];
            *(float4*)(a + 4) = *(float4*)&As[k][ty * 8 + 4];
            *(float4*)(b8)     = *(float4*)&Bs[k][tx * 8];
            *(float4*)(b8 + 4) = *(float4*)&Bs[k][tx * 8 + 4];
#pragma unroll
            for (int i = 0; i < 8; i++)
#pragma unroll
                for (int j = 0; j < 8; j++)
                    acc[i][j] = fmaf(a[i], b8[j], acc[i][j]);
        }
        __syncthreads();
    }

#pragma unroll
    for (int i = 0; i < 8; i++) {
        float4 v0 = make_float4(acc[i][0], acc[i][1], acc[i][2], acc[i][3]);
        float4 v1 = make_float4(acc[i][4], acc[i][5], acc[i][6], acc[i][7]);
        float* crow = Cb + (size_t)(ty * 8 + i) * DMODEL + tx * 8;
        *(float4*)(crow)     = v0;
        *(float4*)(crow + 4) = v1;
    }
}

// ============================================================
// attn_kernel: for a 16-row t-tile of one (b,h), loop outer heads i:
//   scores = Q_i tile (16x128) @ K_i^T (128x1024) / sqrt(128)
//   softmax rows, accumulate into acc; write acc/8 as `attention`.
// grid: (TSEQ/16, NH, BSZ); 256 threads
// smem: Qs 16x132 | Ks 128x128 (XOR-swizzled) | scoreS 16x1024 | acc 16x1024
// ============================================================
#define ATTN_SMEM_FLOATS (16 * 132 + 128 * 128 + 2 * 16 * 1024)

__global__ __launch_bounds__(256) void attn_kernel(
    const float* __restrict__ Q, const float* __restrict__ Kb, float* __restrict__ attn_out)
{
    extern __shared__ float sm[];
    float* Qs = sm;                    // 16*132
    float* Ks = Qs + 16 * 132;         // 128*128 swizzled
    float* scoreS = Ks + 128 * 128;    // 16*1024
    float* acc = scoreS + 16 * 1024;   // 16*1024

    int tid = threadIdx.x;
    int w = tid >> 5, l = tid & 31;
    int b = blockIdx.z, h = blockIdx.y;
    int t0 = blockIdx.x * 16;

    // compute mapping: warp covers 4 rows x 64 cols (half of a 128-col chunk)
    int crow = (w & 3) * 4 + (l >> 3);   // 0..15
    int chalf = (w >> 2) * 64;           // 0 or 64
    int cl0 = l & 7;                     // distinct bank-group per lane

    for (int idx = tid; idx < 16 * 1024; idx += 256) acc[idx] = 0.f;

    const float scale = 0.08838834764831845f;  // 1/sqrt(128)

    for (int i = 0; i < NH; i++) {
        __syncthreads();
        // load Q tile 16x128
        const float* Qbase = Q + ((size_t)(i * BSZ + b) * TSEQ + t0) * DMODEL + h * HD;
        for (int f = tid; f < 16 * 32; f += 256) {
            int row = f >> 5, c4 = f & 31;
            *(float4*)(Qs + row * 132 + c4 * 4) =
                *(const float4*)(Qbase + (size_t)row * DMODEL + c4 * 4);
        }

        const float* Kbase = Kb + (size_t)(i * BSZ + b) * TSEQ * DMODEL + h * HD;
        for (int ch = 0; ch < 8; ch++) {
            __syncthreads();
            // load K chunk: 128 rows x 128 floats, XOR-swizzled at 16B granularity
            for (int f = tid; f < 128 * 32; f += 256) {
                int row = f >> 5, c4 = f & 31;
                int c4s = c4 ^ (row & 7);
                *(float4*)(Ks + row * 128 + c4s * 4) =
                    *(const float4*)(Kbase + (size_t)(ch * 128 + row) * DMODEL + c4 * 4);
            }
            __syncthreads();

            float sc[8] = {};
            const float* Ksp = Ks + (chalf + cl0) * 128;
            const float* Qrp = Qs + crow * 132;
#pragma unroll 8
            for (int k = 0; k < 128; k += 4) {
                float4 qv = *(const float4*)(Qrp + k);
                int f4 = (k >> 2) ^ cl0;
#pragma unroll
                for (int j = 0; j < 8; j++) {
                    float4 kv = *(const float4*)(Ksp + j * 1024 + f4 * 4);
                    sc[j] += qv.x * kv.x + qv.y * kv.y + qv.z * kv.z + qv.w * kv.w;
                }
            }
#pragma unroll
            for (int j = 0; j < 8; j++) {
                int cc = chalf + cl0 + 8 * j;
                scoreS[crow * 1024 + ch * 128 + cc] = sc[j] * scale;
            }
        }
        __syncthreads();

        // softmax per row; 16 threads per row (r = tid>>4, seg = tid&15)
        int r = tid >> 4, seg = tid & 15;
        float m = -1e30f;
        for (int c = seg; c < 1024; c += 16) m = fmaxf(m, scoreS[r * 1024 + c]);
#pragma unroll
        for (int off = 8; off; off >>= 1)
            m = fmaxf(m, __shfl_xor_sync(0xffffffffu, m, off));
        float ssum = 0.f;
        for (int c = seg; c < 1024; c += 16) {
            float p = __expf(scoreS[r * 1024 + c] - m);
            scoreS[r * 1024 + c] = p;
            ssum += p;
        }
#pragma unroll
        for (int off = 8; off; off >>= 1)
            ssum += __shfl_xor_sync(0xffffffffu, ssum, off);
        float inv = 1.0f / ssum;
        for (int c = seg; c < 1024; c += 16)
            acc[r * 1024 + c] += scoreS[r * 1024 + c] * inv;
    }
    __syncthreads();

    // write attention output (mean over i = acc / 8)
    float* outb = attn_out + ((size_t)(b * NH + h) * TSEQ + t0) * TSEQ;
    for (int idx = tid; idx < 16 * 1024; idx += 256)
        outb[idx] = acc[idx] * 0.125f;
}

// ============================================================
extern "C" void kernel_launch(void* const* d_in, const int* in_sizes, int n_in,
                              void* d_out, int out_size) {
    (void)in_sizes; (void)n_in; (void)out_size;
    const float* query = (const float*)d_in[0];
    const float* key   = (const float*)d_in[1];
    const float* value = (const float*)d_in[2];
    const float* Wq    = (const float*)d_in[3];
    const float* Wk    = (const float*)d_in[4];
    const float* Wv    = (const float*)d_in[5];
    const float* Wo    = (const float*)d_in[6];

    float* out = (float*)d_out;                       // outputs: (B,T,D)
    float* out_attn = out + (size_t)BSZ * TSEQ * DMODEL;  // attention: (B,H,T,T)

    float *pQ, *pK, *pV, *pH;
    cudaGetSymbolAddress((void**)&pQ, g_Q);
    cudaGetSymbolAddress((void**)&pK, g_K);
    cudaGetSymbolAddress((void**)&pV, g_V);
    cudaGetSymbolAddress((void**)&pH, g_head);

    const size_t attn_smem = ATTN_SMEM_FLOATS * sizeof(float);
    cudaFuncSetAttribute(attn_kernel, cudaFuncAttributeMaxDynamicSharedMemorySize,
                         (int)attn_smem);

    dim3 blk(256);

    // Q_i = query @ Wq[i]^T, K_i = key @ Wk[i]^T  (batched over i)
    sgemm_abt<<<dim3(DMODEL / 128, BT / 128, NH), blk>>>(
        query, Wq, pQ, DMODEL, DMODEL, DMODEL, DMODEL,
        0L, (long)DMODEL * DMODEL, (long)BT * DMODEL);
    sgemm_abt<<<dim3(DMODEL / 128, BT / 128, NH), blk>>>(
        key, Wk, pK, DMODEL, DMODEL, DMODEL, DMODEL,
        0L, (long)DMODEL * DMODEL, (long)BT * DMODEL);
    // V = value @ Wv^T
    sgemm_abt<<<dim3(DMODEL / 128, BT / 128, 1), blk>>>(
        value, Wv, pV, DMODEL, DMODEL, DMODEL, DMODEL, 0L, 0L, 0L);

    // attention = mean_i softmax(Q_i K_i^T / sqrt(128))  -> second output
    attn_kernel<<<dim3(TSEQ / 16, NH, BSZ), blk, attn_smem>>>(pQ, pK, out_attn);

    // head = attention @ V  (per b,h)
    head_gemm<<<dim3(1, TSEQ / 128, BSZ * NH), blk>>>(out_attn, pV, pH);

    // outputs = head @ Wo^T
    sgemm_abt<<<dim3(DMODEL / 128, BT / 128, 1), blk>>>(
        pH, Wo, out, DMODEL, DMODEL, DMODEL, DMODEL, 0L, 0L, 0L);
}

// round 2
// speedup vs baseline: 1.0029x; 1.0029x over previous
#include <cuda_runtime.h>

#define BSZ 2
#define TSEQ 1024
#define DMODEL 1024
#define NH 8
#define HD 128
#define BT (BSZ * TSEQ)   // 2048

// -------- scratch (no cudaMalloc allowed) --------
__device__ float g_Q[NH * BSZ * TSEQ * DMODEL];   // 67 MB
__device__ float g_K[NH * BSZ * TSEQ * DMODEL];   // 67 MB
__device__ float g_V[BSZ * TSEQ * DMODEL];        // 8 MB
__device__ float g_head[BSZ * TSEQ * DMODEL];     // 8 MB

// ============================================================
// C[m,n] = sum_k A[m,k] * B[n,k]   (A MxK row-major, B NxK row-major)
// grid: (N/128, M/128, batch); 256 threads; 8x8 per thread, BK=16
// ============================================================
__global__ __launch_bounds__(256) void sgemm_abt(
    const float* __restrict__ A, const float* __restrict__ B, float* __restrict__ C,
    int K, int lda, int ldb, int ldc,
    long sA, long sB, long sC)
{
    __shared__ float As[16][132];
    __shared__ float Bs[16][132];

    const float* Ab = A + (size_t)blockIdx.z * sA + (size_t)blockIdx.y * 128 * lda;
    const float* Bb = B + (size_t)blockIdx.z * sB + (size_t)blockIdx.x * 128 * ldb;
    float* Cb = C + (size_t)blockIdx.z * sC + (size_t)blockIdx.y * 128 * ldc + blockIdx.x * 128;

    int tid = threadIdx.x;
    int tx = tid & 15, ty = tid >> 4;
    int lrow = tid >> 2;
    int lq = (tid & 3) * 4;

    float acc[8][8] = {};

    for (int k0 = 0; k0 < K; k0 += 16) {
#pragma unroll
        for (int half = 0; half < 2; half++) {
            int row = lrow + half * 64;
            float4 av = *(const float4*)(Ab + (size_t)row * lda + k0 + lq);
            float4 bv = *(const float4*)(Bb + (size_t)row * ldb + k0 + lq);
            As[lq + 0][row] = av.x; As[lq + 1][row] = av.y;
            As[lq + 2][row] = av.z; As[lq + 3][row] = av.w;
            Bs[lq + 0][row] = bv.x; Bs[lq + 1][row] = bv.y;
            Bs[lq + 2][row] = bv.z; Bs[lq + 3][row] = bv.w;
        }
        __syncthreads();
#pragma unroll
        for (int k = 0; k < 16; k++) {
            float a[8], b8[8];
            *(float4*)(a)     = *(float4*)&As[k][ty * 8];
            *(float4*)(a + 4) = *(float4*)&As[k][ty * 8 + 4];
            *(float4*)(b8)     = *(float4*)&Bs[k][tx * 8];
            *(float4*)(b8 + 4) = *(float4*)&Bs[k][tx * 8 + 4];
#pragma unroll
            for (int i = 0; i < 8; i++)
#pragma unroll
                for (int j = 0; j < 8; j++)
                    acc[i][j] = fmaf(a[i], b8[j], acc[i][j]);
        }
        __syncthreads();
    }

#pragma unroll
    for (int i = 0; i < 8; i++) {
        float4 v0 = make_float4(acc[i][0], acc[i][1], acc[i][2], acc[i][3]);
        float4 v1 = make_float4(acc[i][4], acc[i][5], acc[i][6], acc[i][7]);
        float* crow = Cb + (size_t)(ty * 8 + i) * ldc + tx * 8;
        *(float4*)(crow)     = v0;
        *(float4*)(crow + 4) = v1;
    }
}

// ============================================================
// head_gemm: per (b,h): C[t, e] = sum_s attn[b,h,t,s] * V[b, s, h*128+e]
// grid: (1, TSEQ/128, BSZ*NH); 256 threads; 8x8 per thread, BK=16
// ============================================================
__global__ __launch_bounds__(256) void head_gemm(
    const float* __restrict__ attn, const float* __restrict__ V, float* __restrict__ Ch)
{
    int z = blockIdx.z, b = z >> 3, h = z & 7;
    const float* Ab = attn + (size_t)z * TSEQ * TSEQ + (size_t)blockIdx.y * 128 * TSEQ;
    const float* Bb = V + (size_t)b * TSEQ * DMODEL + h * HD;
    float* Cb = g_head + (size_t)b * TSEQ * DMODEL + (size_t)blockIdx.y * 128 * DMODEL + h * HD;
    (void)Ch;

    __shared__ float As[16][132];
    __shared__ float Bs[16][128];

    int tid = threadIdx.x;
    int tx = tid & 15, ty = tid >> 4;
    int lrow = tid >> 2;
    int lq = (tid & 3) * 4;

    float acc[8][8] = {};

    for (int k0 = 0; k0 < TSEQ; k0 += 16) {
#pragma unroll
        for (int half = 0; half < 2; half++) {
            int row = lrow + half * 64;
            float4 av = *(const float4*)(Ab + (size_t)row * TSEQ + k0 + lq);
            As[lq + 0][row] = av.x; As[lq + 1][row] = av.y;
            As[lq + 2][row] = av.z; As[lq + 3][row] = av.w;
        }
#pragma unroll
        for (int it = 0; it < 2; it++) {
            int f = tid + it * 256;
            int kr = f >> 5, c4 = f & 31;
            *(float4*)(&Bs[kr][c4 * 4]) =
                *(const float4*)(Bb + (size_t)(k0 + kr) * DMODEL + c4 * 4);
        }
        __syncthreads();
#pragma unroll
        for (int k = 0; k < 16; k++) {
            float a[8], b8[8];
            *(float4*)(a)     = *(float4*)&As[k][ty * 8];
            *(float4*)(a + 4) = *(float4*)&As[k][ty * 8 + 4];
            *(float4*)(b8)     = *(float4*)&Bs[k][tx * 8];
            *(float4*)(b8 + 4) = *(float4*)&Bs[k][tx * 8 + 4];
#pragma unroll
            for (int i = 0; i < 8; i++)
#pragma unroll
                for (int j = 0; j < 8; j++)
                    acc[i][j] = fmaf(a[i], b8[j], acc[i][j]);
        }
        __syncthreads();
    }

#pragma unroll
    for (int i = 0; i < 8; i++) {
        float4 v0 = make_float4(acc[i][0], acc[i][1], acc[i][2], acc[i][3]);
        float4 v1 = make_float4(acc[i][4], acc[i][5], acc[i][6], acc[i][7]);
        float* crow = Cb + (size_t)(ty * 8 + i) * DMODEL + tx * 8;
        *(float4*)(crow)     = v0;
        *(float4*)(crow + 4) = v1;
    }
}

// ============================================================
// attn_kernel: for a 16-row t-tile of one (b,h), loop outer heads i:
//   scores = Q_i tile (16x128) @ K_i^T (128x1024) / sqrt(128)
//   softmax rows, accumulate into acc; write acc/8 as `attention`.
// grid: (TSEQ/16, NH, BSZ); 256 threads
// smem: Qs 16x132 | Ks 128x128 (XOR-swizzled) | scoreS 16x1024 | acc 16x1024
// ============================================================
#define ATTN_SMEM_FLOATS (16 * 132 + 128 * 128 + 2 * 16 * 1024)

__global__ __launch_bounds__(256) void attn_kernel(
    const float* __restrict__ Q, const float* __restrict__ Kb, float* __restrict__ attn_out)
{
    extern __shared__ float sm[];
    float* Qs = sm;                    // 16*132
    float* Ks = Qs + 16 * 132;         // 128*128 swizzled
    float* scoreS = Ks + 128 * 128;    // 16*1024
    float* acc = scoreS + 16 * 1024;   // 16*1024

    int tid = threadIdx.x;
    int w = tid >> 5, l = tid & 31;
    int b = blockIdx.z, h = blockIdx.y;
    int t0 = blockIdx.x * 16;

    // compute mapping: warp covers 4 rows x 64 cols (half of a 128-col chunk)
    int crow = (w & 3) * 4 + (l >> 3);   // 0..15
    int chalf = (w >> 2) * 64;           // 0 or 64
    int cl0 = l & 7;                     // distinct bank-group per lane

    for (int idx = tid; idx < 16 * 1024; idx += 256) acc[idx] = 0.f;

    const float scale = 0.08838834764831845f;  // 1/sqrt(128)

    for (int i = 0; i < NH; i++) {
        __syncthreads();
        // load Q tile 16x128
        const float* Qbase = Q + ((size_t)(i * BSZ + b) * TSEQ + t0) * DMODEL + h * HD;
        for (int f = tid; f < 16 * 32; f += 256) {
            int row = f >> 5, c4 = f & 31;
            *(float4*)(Qs + row * 132 + c4 * 4) =
                *(const float4*)(Qbase + (size_t)row * DMODEL + c4 * 4);
        }

        const float* Kbase = Kb + (size_t)(i * BSZ + b) * TSEQ * DMODEL + h * HD;
        for (int ch = 0; ch < 8; ch++) {
            __syncthreads();
            // load K chunk: 128 rows x 128 floats, XOR-swizzled at 16B granularity
            for (int f = tid; f < 128 * 32; f += 256) {
                int row = f >> 5, c4 = f & 31;
                int c4s = c4 ^ (row & 7);
                *(float4*)(Ks + row * 128 + c4s * 4) =
                    *(const float4*)(Kbase + (size_t)(ch * 128 + row) * DMODEL + c4 * 4);
            }
            __syncthreads();

            float sc[8] = {};
            const float* Ksp = Ks + (chalf + cl0) * 128;
            const float* Qrp = Qs + crow * 132;
#pragma unroll 8
            for (int k = 0; k < 128; k += 4) {
                float4 qv = *(const float4*)(Qrp + k);
                int f4 = (k >> 2) ^ cl0;
#pragma unroll
                for (int j = 0; j < 8; j++) {
                    float4 kv = *(const float4*)(Ksp + j * 1024 + f4 * 4);
                    sc[j] += qv.x * kv.x + qv.y * kv.y + qv.z * kv.z + qv.w * kv.w;
                }
            }
#pragma unroll
            for (int j = 0; j < 8; j++) {
                int cc = chalf + cl0 + 8 * j;
                scoreS[crow * 1024 + ch * 128 + cc] = sc[j] * scale;
            }
        }
        __syncthreads();

        // softmax per row; 16 threads per row (r = tid>>4, seg = tid&15)
        int r = tid >> 4, seg = tid & 15;
        float m = -1e30f;
        for (int c = seg; c < 1024; c += 16) m = fmaxf(m, scoreS[r * 1024 + c]);
#pragma unroll
        for (int off = 8; off; off >>= 1)
            m = fmaxf(m, __shfl_xor_sync(0xffffffffu, m, off));
        float ssum = 0.f;
        for (int c = seg; c < 1024; c += 16) {
            float p = __expf(scoreS[r * 1024 + c] - m);
            scoreS[r * 1024 + c] = p;
            ssum += p;
        }
#pragma unroll
        for (int off = 8; off; off >>= 1)
            ssum += __shfl_xor_sync(0xffffffffu, ssum, off);
        float inv = 1.0f / ssum;
        for (int c = seg; c < 1024; c += 16)
            acc[r * 1024 + c] += scoreS[r * 1024 + c] * inv;
    }
    __syncthreads();

    // write attention output (mean over i = acc / 8)
    float* outb = attn_out + ((size_t)(b * NH + h) * TSEQ + t0) * TSEQ;
    for (int idx = tid; idx < 16 * 1024; idx += 256)
        outb[idx] = acc[idx] * 0.125f;
}

// ============================================================
extern "C" void kernel_launch(void* const* d_in, const int* in_sizes, int n_in,
                              void* d_out, int out_size) {
    (void)in_sizes; (void)n_in; (void)out_size;
    const float* query = (const float*)d_in[0];
    const float* key   = (const float*)d_in[1];
    const float* value = (const float*)d_in[2];
    const float* Wq    = (const float*)d_in[3];
    const float* Wk    = (const float*)d_in[4];
    const float* Wv    = (const float*)d_in[5];
    const float* Wo    = (const float*)d_in[6];

    float* out = (float*)d_out;                       // outputs: (B,T,D)
    float* out_attn = out + (size_t)BSZ * TSEQ * DMODEL;  // attention: (B,H,T,T)

    float *pQ, *pK, *pV, *pH;
    cudaGetSymbolAddress((void**)&pQ, g_Q);
    cudaGetSymbolAddress((void**)&pK, g_K);
    cudaGetSymbolAddress((void**)&pV, g_V);
    cudaGetSymbolAddress((void**)&pH, g_head);

    const size_t attn_smem = ATTN_SMEM_FLOATS * sizeof(float);
    cudaFuncSetAttribute(attn_kernel, cudaFuncAttributeMaxDynamicSharedMemorySize,
                         (int)attn_smem);

    dim3 blk(256);

    // Q_i = query @ Wq[i]^T, K_i = key @ Wk[i]^T  (batched over i)
    sgemm_abt<<<dim3(DMODEL / 128, BT / 128, NH), blk>>>(
        query, Wq, pQ, DMODEL, DMODEL, DMODEL, DMODEL,
        0L, (long)DMODEL * DMODEL, (long)BT * DMODEL);
    sgemm_abt<<<dim3(DMODEL / 128, BT / 128, NH), blk>>>(
        key, Wk, pK, DMODEL, DMODEL, DMODEL, DMODEL,
        0L, (long)DMODEL * DMODEL, (long)BT * DMODEL);
    // V = value @ Wv^T
    sgemm_abt<<<dim3(DMODEL / 128, BT / 128, 1), blk>>>(
        value, Wv, pV, DMODEL, DMODEL, DMODEL, DMODEL, 0L, 0L, 0L);

    // attention = mean_i softmax(Q_i K_i^T / sqrt(128))  -> second output
    attn_kernel<<<dim3(TSEQ / 16, NH, BSZ), blk, attn_smem>>>(pQ, pK, out_attn);

    // head = attention @ V  (per b,h)
    head_gemm<<<dim3(1, TSEQ / 128, BSZ * NH), blk>>>(out_attn, pV, pH);

    // outputs = head @ Wo^T
    sgemm_abt<<<dim3(DMODEL / 128, BT / 128, 1), blk>>>(
        pH, Wo, out, DMODEL, DMODEL, DMODEL, DMODEL, 0L, 0L, 0L);
}

// round 4
// speedup vs baseline: 3.9041x; 3.8927x over previous
#include <cuda_runtime.h>
#include <cuda_bf16.h>
#include <cstdint>

#define BSZ 2
#define TSEQ 1024
#define DMODEL 1024
#define NH 8
#define HD 128
#define BT (BSZ * TSEQ)

// ===================== low-level helpers (sm_80+ instructions only) =====================
__device__ __forceinline__ uint32_t smem_u32(const void* p) {
    uint32_t a;
    asm("{ .reg .u64 t; cvta.to.shared.u64 t, %1; cvt.u32.u64 %0, t; }" : "=r"(a) : "l"(p));
    return a;
}
#define CP_ASYNC16(sm_addr, gptr) \
    asm volatile("cp.async.cg.shared.global [%0], [%1], 16;" :: "r"(sm_addr), "l"(gptr))
#define CP_COMMIT() asm volatile("cp.async.commit_group;")
#define CP_WAIT0()  asm volatile("cp.async.wait_group 0;")
#define CP_WAIT1()  asm volatile("cp.async.wait_group 1;")

__device__ __forceinline__ void ldm4(uint32_t* r, uint32_t a) {
    asm volatile("ldmatrix.sync.aligned.m8n8.x4.shared.b16 {%0,%1,%2,%3}, [%4];"
                 : "=r"(r[0]), "=r"(r[1]), "=r"(r[2]), "=r"(r[3]) : "r"(a));
}
__device__ __forceinline__ void ldm2(uint32_t* r, uint32_t a) {
    asm volatile("ldmatrix.sync.aligned.m8n8.x2.shared.b16 {%0,%1}, [%2];"
                 : "=r"(r[0]), "=r"(r[1]) : "r"(a));
}
__device__ __forceinline__ void mma_bf(float* c, const uint32_t* a, const uint32_t* b) {
    asm volatile(
        "mma.sync.aligned.m16n8k16.row.col.f32.bf16.bf16.f32 "
        "{%0,%1,%2,%3}, {%4,%5,%6,%7}, {%8,%9}, {%0,%1,%2,%3};"
        : "+f"(c[0]), "+f"(c[1]), "+f"(c[2]), "+f"(c[3])
        : "r"(a[0]), "r"(a[1]), "r"(a[2]), "r"(a[3]), "r"(b[0]), "r"(b[1]));
}
// tiles are 128 rows x 64 bf16 (128B rows) with 16B-granular XOR swizzle
__device__ __forceinline__ uint32_t swz(uint32_t base, int row, int kbytes) {
    uint32_t bo = (uint32_t)(row * 128 + kbytes);
    return base + (bo ^ ((bo >> 3) & 0x70));
}
// async copy of one 128x64 bf16 tile into swizzled SMEM; 256 threads
__device__ __forceinline__ void tile_cp(uint32_t sdst, const __nv_bfloat16* __restrict__ src,
                                        int rstride, int tid) {
#pragma unroll
    for (int it = 0; it < 4; it++) {
        int f = tid + it * 256;
        int row = f >> 3, c8 = (f & 7) << 3;
        uint32_t bo = (uint32_t)(row * 128 + c8 * 2);
        uint32_t sw = bo ^ ((bo >> 3) & 0x70);
        CP_ASYNC16(sdst + sw, src + (size_t)row * rstride + c8);
    }
}
__device__ __forceinline__ void bsplit(float v, __nv_bfloat16& h, __nv_bfloat16& l) {
    h = __float2bfloat16(v);
    l = __float2bfloat16(v - __bfloat162float(h));
}
__device__ __forceinline__ uint32_t pack_bf2(__nv_bfloat16 a, __nv_bfloat16 b) {
    __nv_bfloat162 t; t.x = a; t.y = b;
    return *reinterpret_cast<uint32_t*>(&t);
}

// ===================== scratch offsets (bf16 elements) =====================
#define MEG 1048576LL
#define O_QRH (0LL)
#define O_QRL (2 * MEG)
#define O_KYH (4 * MEG)
#define O_KYL (6 * MEG)
#define O_VAH (8 * MEG)
#define O_VAL (10 * MEG)
#define O_WQH (12 * MEG)
#define O_WQL (20 * MEG)
#define O_WKH (28 * MEG)
#define O_WKL (36 * MEG)
#define O_WVH (44 * MEG)
#define O_WVL (45 * MEG)
#define O_WOH (46 * MEG)
#define O_WOL (47 * MEG)
#define O_QH  (48 * MEG)
#define O_QL  (64 * MEG)
#define O_KH  (80 * MEG)
#define O_KL  (96 * MEG)
#define O_VTH (112 * MEG)
#define O_VTL (114 * MEG)
#define O_PH  (116 * MEG)
#define O_PL  (132 * MEG)
#define O_HH  (148 * MEG)
#define O_HL  (150 * MEG)
#define SCRATCH_ELEMS (152 * MEG)
__device__ __nv_bfloat16 g_bf[SCRATCH_ELEMS];

// ===================== fp32 -> bf16 hi/lo split =====================
__global__ __launch_bounds__(256) void cvt_k(const float* __restrict__ x,
                                             __nv_bfloat16* __restrict__ hi,
                                             __nv_bfloat16* __restrict__ lo, int n4) {
    int i = blockIdx.x * 256 + threadIdx.x;
    if (i >= n4) return;
    float4 v = reinterpret_cast<const float4*>(x)[i];
    __nv_bfloat16 h0, h1, h2, h3, l0, l1, l2, l3;
    bsplit(v.x, h0, l0); bsplit(v.y, h1, l1); bsplit(v.z, h2, l2); bsplit(v.w, h3, l3);
    reinterpret_cast<uint2*>(hi)[i] = make_uint2(pack_bf2(h0, h1), pack_bf2(h2, h3));
    reinterpret_cast<uint2*>(lo)[i] = make_uint2(pack_bf2(l0, l1), pack_bf2(l2, l3));
}

// ===================== generic bf16x3 GEMM: C = A @ B^T (HMMA) =====================
// A: M x K row-major, B: N x K row-major (bf16 hi/lo pairs). CTA tile 128x128,
// warps 2(m) x 4(n), warp tile 64x32, K-chunks of 64, 2-stage cp.async pipeline.
// modes: 0 = fp32 C; 1 = bf16-split C; 2 = bf16-split transposed (Vt[b][n][s])
#define G_SMEM 131072   // 2 stages x (Ahi|Alo|Bhi|Blo) x 16KB

__global__ __launch_bounds__(256) void gemm_bx3(
    const __nv_bfloat16* __restrict__ Ahi, const __nv_bfloat16* __restrict__ Alo,
    const __nv_bfloat16* __restrict__ Bhi, const __nv_bfloat16* __restrict__ Blo,
    float* __restrict__ Cf, __nv_bfloat16* __restrict__ Chi, __nv_bfloat16* __restrict__ Clo,
    int kchunks, int lda, int ldb, int ldc, int zdiv,
    long long sA1, long long sA2, long long sB1, long long sB2,
    long long sC1, long long sC2, int mode)
{
    extern __shared__ __align__(1024) char sm[];
    int tid = threadIdx.x, wid = tid >> 5, l = tid & 31;
    int wm = wid >> 2, wn = wid & 3;
    uint32_t sb = smem_u32(sm);

    long long zq = blockIdx.z / zdiv, zr = blockIdx.z % zdiv;
    const __nv_bfloat16* A0 = Ahi + zq * sA1 + zr * sA2 + (long long)blockIdx.y * 128 * lda;
    const __nv_bfloat16* A1 = Alo + zq * sA1 + zr * sA2 + (long long)blockIdx.y * 128 * lda;
    const __nv_bfloat16* B0 = Bhi + zq * sB1 + zr * sB2 + (long long)blockIdx.x * 128 * ldb;
    const __nv_bfloat16* B1 = Blo + zq * sB1 + zr * sB2 + (long long)blockIdx.x * 128 * ldb;

    float c[4][4][4];
#pragma unroll
    for (int a = 0; a < 4; a++)
#pragma unroll
        for (int b2 = 0; b2 < 4; b2++)
#pragma unroll
            for (int d = 0; d < 4; d++) c[a][b2][d] = 0.f;

    // prologue
    {
        uint32_t bo = sb;
        tile_cp(bo,         A0, lda, tid);
        tile_cp(bo + 16384, A1, lda, tid);
        tile_cp(bo + 32768, B0, ldb, tid);
        tile_cp(bo + 49152, B1, ldb, tid);
        CP_COMMIT();
    }
    for (int ck = 0; ck < kchunks; ck++) {
        if (ck + 1 < kchunks) {
            uint32_t bo = sb + ((ck + 1) & 1) * 65536;
            tile_cp(bo,         A0 + (ck + 1) * 64, lda, tid);
            tile_cp(bo + 16384, A1 + (ck + 1) * 64, lda, tid);
            tile_cp(bo + 32768, B0 + (ck + 1) * 64, ldb, tid);
            tile_cp(bo + 49152, B1 + (ck + 1) * 64, ldb, tid);
            CP_COMMIT();
            CP_WAIT1();
        } else {
            CP_WAIT0();
        }
        __syncthreads();
        uint32_t bo = sb + (ck & 1) * 65536;
#pragma unroll
        for (int s16 = 0; s16 < 4; s16++) {
            int kb = s16 * 16;
            uint32_t bh[4][2], bl[4][2];
#pragma unroll
            for (int nt = 0; nt < 4; nt++) {
                uint32_t ad = swz(bo + 32768, wn * 32 + nt * 8 + (l & 7),
                                  (kb + ((l >> 3) & 1) * 8) * 2);
                ldm2(bh[nt], ad);
                ldm2(bl[nt], ad + 16384);
            }
#pragma unroll
            for (int mt = 0; mt < 4; mt++) {
                uint32_t ah[4], al[4];
                uint32_t aa = swz(bo, wm * 64 + mt * 16 + (l & 15),
                                  (kb + ((l >> 4) & 1) * 8) * 2);
                ldm4(ah, aa);
                ldm4(al, aa + 16384);
#pragma unroll
                for (int nt = 0; nt < 4; nt++) {
                    mma_bf(c[mt][nt], ah, bh[nt]);
                    mma_bf(c[mt][nt], ah, bl[nt]);
                    mma_bf(c[mt][nt], al, bh[nt]);
                }
            }
        }
        __syncthreads();
    }

    // epilogue
    int g = l >> 2, q2 = (l & 3) * 2;
    long long czb = zq * sC1 + zr * sC2;
#pragma unroll
    for (int mt = 0; mt < 4; mt++) {
        long long m0 = (long long)blockIdx.y * 128 + wm * 64 + mt * 16 + g;
        long long m1 = m0 + 8;
#pragma unroll
        for (int nt = 0; nt < 4; nt++) {
            int n0 = blockIdx.x * 128 + wn * 32 + nt * 8 + q2;
            float* cc = c[mt][nt];
            if (mode == 0) {
                *reinterpret_cast<float2*>(Cf + czb + m0 * ldc + n0) = make_float2(cc[0], cc[1]);
                *reinterpret_cast<float2*>(Cf + czb + m1 * ldc + n0) = make_float2(cc[2], cc[3]);
            } else if (mode == 1) {
                __nv_bfloat16 h0, l0, h1, l1;
                bsplit(cc[0], h0, l0); bsplit(cc[1], h1, l1);
                *reinterpret_cast<uint32_t*>(Chi + czb + m0 * ldc + n0) = pack_bf2(h0, h1);
                *reinterpret_cast<uint32_t*>(Clo + czb + m0 * ldc + n0) = pack_bf2(l0, l1);
                bsplit(cc[2], h0, l0); bsplit(cc[3], h1, l1);
                *reinterpret_cast<uint32_t*>(Chi + czb + m1 * ldc + n0) = pack_bf2(h0, h1);
                *reinterpret_cast<uint32_t*>(Clo + czb + m1 * ldc + n0) = pack_bf2(l0, l1);
            } else {
                // transposed split store: Chi[b][n][s], m -> (b, s)
#pragma unroll
                for (int half = 0; half < 2; half++) {
                    long long m = half ? m1 : m0;
                    int bb = (int)(m >> 10), ss = (int)(m & 1023);
                    long long base = (long long)bb * DMODEL * TSEQ + ss;
#pragma unroll
                    for (int j = 0; j < 2; j++) {
                        __nv_bfloat16 hh, ll;
                        bsplit(cc[half * 2 + j], hh, ll);
                        Chi[base + (long long)(n0 + j) * TSEQ] = hh;
                        Clo[base + (long long)(n0 + j) * TSEQ] = ll;
                    }
                }
            }
        }
    }
}

// ===================== fused attention (HMMA scores + max-free softmax) =====================
// grid (TSEQ/128, NH, BSZ), 256 threads. Per CTA: 128 t-rows of one (b,h).
// pass 0: row sums of exp(scores) per outer head i (deterministic reduction).
// pass 1: recompute scores, normalize, accumulate mean over i in registers, store.
#define AT_RSPART 131072
#define AT_RS128  133120
#define AT_RSF    133632
#define AT_SMEM   137728

__global__ __launch_bounds__(256) void attn_mma(
    const __nv_bfloat16* __restrict__ Qh, const __nv_bfloat16* __restrict__ Ql,
    const __nv_bfloat16* __restrict__ Kh, const __nv_bfloat16* __restrict__ Kl,
    float* __restrict__ attn_out, __nv_bfloat16* __restrict__ Ph, __nv_bfloat16* __restrict__ Pl)
{
    extern __shared__ __align__(1024) char sm[];
    int tid = threadIdx.x, wid = tid >> 5, l = tid & 31;
    int wm = wid >> 2, wn = wid & 3;
    uint32_t sb = smem_u32(sm);
    float* rspart = reinterpret_cast<float*>(sm + AT_RSPART);  // 128 rows x 4 warp_n
    float* rs128  = reinterpret_cast<float*>(sm + AT_RS128);   // 128
    float* rsf    = reinterpret_cast<float*>(sm + AT_RSF);     // 8 x 128

    int b = blockIdx.z, h = blockIdx.y, t0 = blockIdx.x * 128;
    const float SC = 0.08838834764831845f;   // 1/sqrt(128)
    int g = l >> 2, q2 = (l & 3) * 2;

    if (tid < 128) rs128[tid] = 0.f;
    __syncthreads();

    float c[4][4][4];
    float pacc[4][4][4];
#pragma unroll
    for (int a = 0; a < 4; a++)
#pragma unroll
        for (int b2 = 0; b2 < 4; b2++)
#pragma unroll
            for (int d = 0; d < 4; d++) { c[a][b2][d] = 0.f; pacc[a][b2][d] = 0.f; }

    for (int pass = 0; pass < 2; pass++) {
        const int S = 128;   // 8i x 8ch x 2 k-halves
        // stage source decode
        auto stage_load = [&](int s, int buf) {
            int kh = s & 1, t = s >> 1, i, ch;
            if (pass == 0) { i = t >> 3; ch = t & 7; }
            else           { ch = t >> 3; i = t & 7; }
            size_t qb = ((size_t)(i * BSZ + b) * TSEQ + t0) * DMODEL + h * HD + kh * 64;
            size_t kb = ((size_t)(i * BSZ + b) * TSEQ + ch * 128) * DMODEL + h * HD + kh * 64;
            uint32_t bo = sb + buf * 65536;
            tile_cp(bo,         Qh + qb, DMODEL, tid);
            tile_cp(bo + 16384, Ql + qb, DMODEL, tid);
            tile_cp(bo + 32768, Kh + kb, DMODEL, tid);
            tile_cp(bo + 49152, Kl + kb, DMODEL, tid);
            CP_COMMIT();
        };
        stage_load(0, 0);
        for (int s = 0; s < S; s++) {
            if (s + 1 < S) { stage_load(s + 1, (s + 1) & 1); CP_WAIT1(); }
            else           { CP_WAIT0(); }
            __syncthreads();
            uint32_t bo = sb + (s & 1) * 65536;
#pragma unroll
            for (int s16 = 0; s16 < 4; s16++) {
                int kb = s16 * 16;
                uint32_t bh[4][2], bl[4][2];
#pragma unroll
                for (int nt = 0; nt < 4; nt++) {
                    uint32_t ad = swz(bo + 32768, wn * 32 + nt * 8 + (l & 7),
                                      (kb + ((l >> 3) & 1) * 8) * 2);
                    ldm2(bh[nt], ad);
                    ldm2(bl[nt], ad + 16384);
                }
#pragma unroll
                for (int mt = 0; mt < 4; mt++) {
                    uint32_t ah[4], al[4];
                    uint32_t aa = swz(bo, wm * 64 + mt * 16 + (l & 15),
                                      (kb + ((l >> 4) & 1) * 8) * 2);
                    ldm4(ah, aa);
                    ldm4(al, aa + 16384);
#pragma unroll
                    for (int nt = 0; nt < 4; nt++) {
                        mma_bf(c[mt][nt], ah, bh[nt]);
                        mma_bf(c[mt][nt], ah, bl[nt]);
                        mma_bf(c[mt][nt], al, bh[nt]);
                    }
                }
            }
            int kh = s & 1, t = s >> 1, i, ch;
            if (pass == 0) { i = t >> 3; ch = t & 7; }
            else           { ch = t >> 3; i = t & 7; }
            if (kh == 1) {
                if (pass == 0) {
                    float ps[8];
#pragma unroll
                    for (int mt = 0; mt < 4; mt++) {
                        float s0 = 0.f, s1 = 0.f;
#pragma unroll
                        for (int nt = 0; nt < 4; nt++) {
                            s0 += __expf(c[mt][nt][0] * SC) + __expf(c[mt][nt][1] * SC);
                            s1 += __expf(c[mt][nt][2] * SC) + __expf(c[mt][nt][3] * SC);
                        }
                        ps[2 * mt] = s0; ps[2 * mt + 1] = s1;
                    }
#pragma unroll
                    for (int off = 1; off <= 2; off <<= 1)
#pragma unroll
                        for (int k = 0; k < 8; k++)
                            ps[k] += __shfl_xor_sync(0xffffffffu, ps[k], off);
                    if ((l & 3) == 0) {
#pragma unroll
                        for (int mt = 0; mt < 4; mt++) {
                            int r0 = wm * 64 + mt * 16 + g;
                            rspart[r0 * 4 + wn] = ps[2 * mt];
                            rspart[(r0 + 8) * 4 + wn] = ps[2 * mt + 1];
                        }
                    }
                    __syncthreads();
                    if (tid < 128) {
                        rs128[tid] += rspart[tid * 4] + rspart[tid * 4 + 1] +
                                      rspart[tid * 4 + 2] + rspart[tid * 4 + 3];
                        if (ch == 7) {
                            rsf[i * 128 + tid] = 0.125f / rs128[tid];  // fold mean over i
                            rs128[tid] = 0.f;
                        }
                    }
                } else {
                    float inv0[4], inv1[4];
#pragma unroll
                    for (int mt = 0; mt < 4; mt++) {
                        int r0 = wm * 64 + mt * 16 + g;
                        inv0[mt] = rsf[i * 128 + r0];
                        inv1[mt] = rsf[i * 128 + r0 + 8];
                    }
#pragma unroll
                    for (int mt = 0; mt < 4; mt++)
#pragma unroll
                        for (int nt = 0; nt < 4; nt++) {
                            pacc[mt][nt][0] += __expf(c[mt][nt][0] * SC) * inv0[mt];
                            pacc[mt][nt][1] += __expf(c[mt][nt][1] * SC) * inv0[mt];
                            pacc[mt][nt][2] += __expf(c[mt][nt][2] * SC) * inv1[mt];
                            pacc[mt][nt][3] += __expf(c[mt][nt][3] * SC) * inv1[mt];
                        }
                    if (i == 7) {
                        size_t ob = ((size_t)(b * NH + h) * TSEQ + t0) * TSEQ;
#pragma unroll
                        for (int mt = 0; mt < 4; mt++) {
                            int r0 = wm * 64 + mt * 16 + g, r1 = r0 + 8;
#pragma unroll
                            for (int nt = 0; nt < 4; nt++) {
                                int col = ch * 128 + wn * 32 + nt * 8 + q2;
                                float* pp = pacc[mt][nt];
                                *reinterpret_cast<float2*>(attn_out + ob + (size_t)r0 * TSEQ + col) =
                                    make_float2(pp[0], pp[1]);
                                *reinterpret_cast<float2*>(attn_out + ob + (size_t)r1 * TSEQ + col) =
                                    make_float2(pp[2], pp[3]);
                                __nv_bfloat16 h0, l0, h1, l1;
                                bsplit(pp[0], h0, l0); bsplit(pp[1], h1, l1);
                                *reinterpret_cast<uint32_t*>(Ph + ob + (size_t)r0 * TSEQ + col) = pack_bf2(h0, h1);
                                *reinterpret_cast<uint32_t*>(Pl + ob + (size_t)r0 * TSEQ + col) = pack_bf2(l0, l1);
                                bsplit(pp[2], h0, l0); bsplit(pp[3], h1, l1);
                                *reinterpret_cast<uint32_t*>(Ph + ob + (size_t)r1 * TSEQ + col) = pack_bf2(h0, h1);
                                *reinterpret_cast<uint32_t*>(Pl + ob + (size_t)r1 * TSEQ + col) = pack_bf2(l0, l1);
                                pp[0] = pp[1] = pp[2] = pp[3] = 0.f;
                            }
                        }
                    }
                }
                // reset score accumulators for next (i,ch)
#pragma unroll
                for (int a = 0; a < 4; a++)
#pragma unroll
                    for (int b2 = 0; b2 < 4; b2++)
#pragma unroll
                        for (int d = 0; d < 4; d++) c[a][b2][d] = 0.f;
            }
            __syncthreads();
        }
    }
}

// ===================== host =====================
extern "C" void kernel_launch(void* const* d_in, const int* in_sizes, int n_in,
                              void* d_out, int out_size) {
    (void)in_sizes; (void)n_in; (void)out_size;
    const float* query = (const float*)d_in[0];
    const float* key   = (const float*)d_in[1];
    const float* value = (const float*)d_in[2];
    const float* Wq    = (const float*)d_in[3];
    const float* Wk    = (const float*)d_in[4];
    const float* Wv    = (const float*)d_in[5];
    const float* Wo    = (const float*)d_in[6];
    float* out = (float*)d_out;
    float* out_attn = out + (size_t)BT * DMODEL;

    __nv_bfloat16* S;
    cudaGetSymbolAddress((void**)&S, g_bf);
#define AT(o) (S + (size_t)(o))

    cudaFuncSetAttribute(gemm_bx3, cudaFuncAttributeMaxDynamicSharedMemorySize, G_SMEM);
    cudaFuncSetAttribute(attn_mma, cudaFuncAttributeMaxDynamicSharedMemorySize, AT_SMEM);

    // splits
    cvt_k<<<2048, 256>>>(query, AT(O_QRH), AT(O_QRL), 524288);
    cvt_k<<<2048, 256>>>(key,   AT(O_KYH), AT(O_KYL), 524288);
    cvt_k<<<2048, 256>>>(value, AT(O_VAH), AT(O_VAL), 524288);
    cvt_k<<<8192, 256>>>(Wq,    AT(O_WQH), AT(O_WQL), 2097152);
    cvt_k<<<8192, 256>>>(Wk,    AT(O_WKH), AT(O_WKL), 2097152);
    cvt_k<<<1024, 256>>>(Wv,    AT(O_WVH), AT(O_WVL), 262144);
    cvt_k<<<1024, 256>>>(Wo,    AT(O_WOH), AT(O_WOL), 262144);

    dim3 blk(256);
    // Q_i = query @ Wq[i]^T (bf16-split out), K_i = key @ Wk[i]^T
    gemm_bx3<<<dim3(8, 16, 8), blk, G_SMEM>>>(
        AT(O_QRH), AT(O_QRL), AT(O_WQH), AT(O_WQL), nullptr, AT(O_QH), AT(O_QL),
        16, DMODEL, DMODEL, DMODEL, 1,
        0LL, 0LL, (long long)DMODEL * DMODEL, 0LL, (long long)BT * DMODEL, 0LL, 1);
    gemm_bx3<<<dim3(8, 16, 8), blk, G_SMEM>>>(
        AT(O_KYH), AT(O_KYL), AT(O_WKH), AT(O_WKL), nullptr, AT(O_KH), AT(O_KL),
        16, DMODEL, DMODEL, DMODEL, 1,
        0LL, 0LL, (long long)DMODEL * DMODEL, 0LL, (long long)BT * DMODEL, 0LL, 1);
    // Vt = (value @ Wv^T)^T (transposed split out)
    gemm_bx3<<<dim3(8, 16, 1), blk, G_SMEM>>>(
        AT(O_VAH), AT(O_VAL), AT(O_WVH), AT(O_WVL), nullptr, AT(O_VTH), AT(O_VTL),
        16, DMODEL, DMODEL, DMODEL, 1, 0LL, 0LL, 0LL, 0LL, 0LL, 0LL, 2);

    // attention (mean over i) + split probs
    attn_mma<<<dim3(TSEQ / 128, NH, BSZ), blk, AT_SMEM>>>(
        AT(O_QH), AT(O_QL), AT(O_KH), AT(O_KL), out_attn, AT(O_PH), AT(O_PL));

    // head[b,t,h*128+e] = sum_s P[b,h,t,s] * Vt[b,h*128+e,s] (split out)
    gemm_bx3<<<dim3(1, 8, 16), blk, G_SMEM>>>(
        AT(O_PH), AT(O_PL), AT(O_VTH), AT(O_VTL), nullptr, AT(O_HH), AT(O_HL),
        16, TSEQ, TSEQ, DMODEL, 8,
        (long long)NH * TSEQ * TSEQ, (long long)TSEQ * TSEQ,
        (long long)DMODEL * TSEQ, (long long)HD * TSEQ,
        (long long)TSEQ * DMODEL, (long long)HD, 1);

    // outputs = head @ Wo^T (fp32)
    gemm_bx3<<<dim3(8, 16, 1), blk, G_SMEM>>>(
        AT(O_HH), AT(O_HL), AT(O_WOH), AT(O_WOL), out, nullptr, nullptr,
        16, DMODEL, DMODEL, DMODEL, 1, 0LL, 0LL, 0LL, 0LL, 0LL, 0LL, 0);
}

// round 5
// speedup vs baseline: 4.1785x; 1.0703x over previous
#include <cuda_runtime.h>
#include <cuda_bf16.h>
#include <cstdint>

#define BSZ 2
#define TSEQ 1024
#define DMODEL 1024
#define NH 8
#define HD 128
#define BT (BSZ * TSEQ)

// ===================== low-level helpers (sm_80+ instructions only) =====================
__device__ __forceinline__ uint32_t smem_u32(const void* p) {
    uint32_t a;
    asm("{ .reg .u64 t; cvta.to.shared.u64 t, %1; cvt.u32.u64 %0, t; }" : "=r"(a) : "l"(p));
    return a;
}
#define CP_ASYNC16(sm_addr, gptr) \
    asm volatile("cp.async.cg.shared.global [%0], [%1], 16;" :: "r"(sm_addr), "l"(gptr))
#define CP_COMMIT() asm volatile("cp.async.commit_group;")
#define CP_WAIT0()  asm volatile("cp.async.wait_group 0;")
#define CP_WAIT1()  asm volatile("cp.async.wait_group 1;")
#define CP_WAIT2()  asm volatile("cp.async.wait_group 2;")

__device__ __forceinline__ void ldm4(uint32_t* r, uint32_t a) {
    asm volatile("ldmatrix.sync.aligned.m8n8.x4.shared.b16 {%0,%1,%2,%3}, [%4];"
                 : "=r"(r[0]), "=r"(r[1]), "=r"(r[2]), "=r"(r[3]) : "r"(a));
}
__device__ __forceinline__ void ldm2(uint32_t* r, uint32_t a) {
    asm volatile("ldmatrix.sync.aligned.m8n8.x2.shared.b16 {%0,%1}, [%2];"
                 : "=r"(r[0]), "=r"(r[1]) : "r"(a));
}
__device__ __forceinline__ void mma_bf(float* c, const uint32_t* a, const uint32_t* b) {
    asm volatile(
        "mma.sync.aligned.m16n8k16.row.col.f32.bf16.bf16.f32 "
        "{%0,%1,%2,%3}, {%4,%5,%6,%7}, {%8,%9}, {%0,%1,%2,%3};"
        : "+f"(c[0]), "+f"(c[1]), "+f"(c[2]), "+f"(c[3])
        : "r"(a[0]), "r"(a[1]), "r"(a[2]), "r"(a[3]), "r"(b[0]), "r"(b[1]));
}
// tiles are 128 rows x 64 bf16 (128B rows) with 16B-granular XOR swizzle
__device__ __forceinline__ uint32_t swz(uint32_t base, int row, int kbytes) {
    uint32_t bo = (uint32_t)(row * 128 + kbytes);
    return base + (bo ^ ((bo >> 3) & 0x70));
}
// async copy of one 128x64 bf16 tile into swizzled SMEM; 256 threads
__device__ __forceinline__ void tile_cp(uint32_t sdst, const __nv_bfloat16* __restrict__ src,
                                        int rstride, int tid) {
#pragma unroll
    for (int it = 0; it < 4; it++) {
        int f = tid + it * 256;
        int row = f >> 3, c8 = (f & 7) << 3;
        uint32_t bo = (uint32_t)(row * 128 + c8 * 2);
        uint32_t sw = bo ^ ((bo >> 3) & 0x70);
        CP_ASYNC16(sdst + sw, src + (size_t)row * rstride + c8);
    }
}
__device__ __forceinline__ void bsplit(float v, __nv_bfloat16& h, __nv_bfloat16& l) {
    h = __float2bfloat16(v);
    l = __float2bfloat16(v - __bfloat162float(h));
}
__device__ __forceinline__ uint32_t pack_bf2(__nv_bfloat16 a, __nv_bfloat16 b) {
    __nv_bfloat162 t; t.x = a; t.y = b;
    return *reinterpret_cast<uint32_t*>(&t);
}

// ===================== scratch offsets (bf16 elements) =====================
#define MEG 1048576LL
#define O_QRH (0LL)
#define O_QRL (2 * MEG)
#define O_KYH (4 * MEG)
#define O_KYL (6 * MEG)
#define O_VAH (8 * MEG)
#define O_VAL (10 * MEG)
#define O_WQH (12 * MEG)
#define O_WQL (20 * MEG)
#define O_WKH (28 * MEG)
#define O_WKL (36 * MEG)
#define O_WVH (44 * MEG)
#define O_WVL (45 * MEG)
#define O_WOH (46 * MEG)
#define O_WOL (47 * MEG)
#define O_QH  (48 * MEG)
#define O_QL  (64 * MEG)
#define O_KH  (80 * MEG)
#define O_KL  (96 * MEG)
#define O_VTH (112 * MEG)
#define O_VTL (114 * MEG)
#define O_PH  (116 * MEG)
#define O_PL  (132 * MEG)
#define O_HH  (148 * MEG)
#define O_HL  (150 * MEG)
#define O_PTH (152 * MEG)            // unnormalized exp hi: 8 x 16M
#define O_PTL (280 * MEG)            // unnormalized exp lo: 8 x 16M
#define SCRATCH_ELEMS (408 * MEG)
__device__ __nv_bfloat16 g_bf[SCRATCH_ELEMS];
__device__ float g_inv[8 * BSZ * NH * TSEQ];   // 0.125/rowsum per (i, b, h, t)

#define PT_PLANE 16777216LL          // BSZ*NH*TSEQ*TSEQ per i

// ===================== fp32 -> bf16 hi/lo split =====================
__global__ __launch_bounds__(256) void cvt_k(const float* __restrict__ x,
                                             __nv_bfloat16* __restrict__ hi,
                                             __nv_bfloat16* __restrict__ lo, int n4) {
    int i = blockIdx.x * 256 + threadIdx.x;
    if (i >= n4) return;
    float4 v = reinterpret_cast<const float4*>(x)[i];
    __nv_bfloat16 h0, h1, h2, h3, l0, l1, l2, l3;
    bsplit(v.x, h0, l0); bsplit(v.y, h1, l1); bsplit(v.z, h2, l2); bsplit(v.w, h3, l3);
    reinterpret_cast<uint2*>(hi)[i] = make_uint2(pack_bf2(h0, h1), pack_bf2(h2, h3));
    reinterpret_cast<uint2*>(lo)[i] = make_uint2(pack_bf2(l0, l1), pack_bf2(l2, l3));
}

// ===================== generic bf16x3 GEMM: C = A @ B^T (HMMA, 3-stage) =====================
#define G_SMEM 196608   // 3 stages x (Ahi|Alo|Bhi|Blo) x 16KB

__global__ __launch_bounds__(256) void gemm_bx3(
    const __nv_bfloat16* __restrict__ Ahi, const __nv_bfloat16* __restrict__ Alo,
    const __nv_bfloat16* __restrict__ Bhi, const __nv_bfloat16* __restrict__ Blo,
    float* __restrict__ Cf, __nv_bfloat16* __restrict__ Chi, __nv_bfloat16* __restrict__ Clo,
    int kchunks, int lda, int ldb, int ldc, int zdiv,
    long long sA1, long long sA2, long long sB1, long long sB2,
    long long sC1, long long sC2, int mode)
{
    extern __shared__ __align__(1024) char sm[];
    int tid = threadIdx.x, wid = tid >> 5, l = tid & 31;
    int wm = wid >> 2, wn = wid & 3;
    uint32_t sb = smem_u32(sm);

    long long zq = blockIdx.z / zdiv, zr = blockIdx.z % zdiv;
    const __nv_bfloat16* A0 = Ahi + zq * sA1 + zr * sA2 + (long long)blockIdx.y * 128 * lda;
    const __nv_bfloat16* A1 = Alo + zq * sA1 + zr * sA2 + (long long)blockIdx.y * 128 * lda;
    const __nv_bfloat16* B0 = Bhi + zq * sB1 + zr * sB2 + (long long)blockIdx.x * 128 * ldb;
    const __nv_bfloat16* B1 = Blo + zq * sB1 + zr * sB2 + (long long)blockIdx.x * 128 * ldb;

    float c[4][4][4];
#pragma unroll
    for (int a = 0; a < 4; a++)
#pragma unroll
        for (int b2 = 0; b2 < 4; b2++)
#pragma unroll
            for (int d = 0; d < 4; d++) c[a][b2][d] = 0.f;

    auto load_chunk = [&](int ck) {
        uint32_t bo = sb + (ck % 3) * 65536;
        tile_cp(bo,         A0 + ck * 64, lda, tid);
        tile_cp(bo + 16384, A1 + ck * 64, lda, tid);
        tile_cp(bo + 32768, B0 + ck * 64, ldb, tid);
        tile_cp(bo + 49152, B1 + ck * 64, ldb, tid);
        CP_COMMIT();
    };
    load_chunk(0);
    if (kchunks > 1) load_chunk(1);

    for (int ck = 0; ck < kchunks; ck++) {
        if (ck + 2 < kchunks) { load_chunk(ck + 2); CP_WAIT2(); }
        else if (ck + 1 < kchunks) CP_WAIT1();
        else CP_WAIT0();
        __syncthreads();
        uint32_t bo = sb + (ck % 3) * 65536;
#pragma unroll
        for (int s16 = 0; s16 < 4; s16++) {
            int kb = s16 * 16;
            uint32_t bh[4][2], bl[4][2];
#pragma unroll
            for (int nt = 0; nt < 4; nt++) {
                uint32_t ad = swz(bo + 32768, wn * 32 + nt * 8 + (l & 7),
                                  (kb + ((l >> 3) & 1) * 8) * 2);
                ldm2(bh[nt], ad);
                ldm2(bl[nt], ad + 16384);
            }
#pragma unroll
            for (int mt = 0; mt < 4; mt++) {
                uint32_t ah[4], al[4];
                uint32_t aa = swz(bo, wm * 64 + mt * 16 + (l & 15),
                                  (kb + ((l >> 4) & 1) * 8) * 2);
                ldm4(ah, aa);
                ldm4(al, aa + 16384);
#pragma unroll
                for (int nt = 0; nt < 4; nt++) {
                    mma_bf(c[mt][nt], ah, bh[nt]);
                    mma_bf(c[mt][nt], ah, bl[nt]);
                    mma_bf(c[mt][nt], al, bh[nt]);
                }
            }
        }
        __syncthreads();
    }

    // epilogue
    int g = l >> 2, q2 = (l & 3) * 2;
    long long czb = zq * sC1 + zr * sC2;
#pragma unroll
    for (int mt = 0; mt < 4; mt++) {
        long long m0 = (long long)blockIdx.y * 128 + wm * 64 + mt * 16 + g;
        long long m1 = m0 + 8;
#pragma unroll
        for (int nt = 0; nt < 4; nt++) {
            int n0 = blockIdx.x * 128 + wn * 32 + nt * 8 + q2;
            float* cc = c[mt][nt];
            if (mode == 0) {
                *reinterpret_cast<float2*>(Cf + czb + m0 * ldc + n0) = make_float2(cc[0], cc[1]);
                *reinterpret_cast<float2*>(Cf + czb + m1 * ldc + n0) = make_float2(cc[2], cc[3]);
            } else if (mode == 1) {
                __nv_bfloat16 h0, l0, h1, l1;
                bsplit(cc[0], h0, l0); bsplit(cc[1], h1, l1);
                *reinterpret_cast<uint32_t*>(Chi + czb + m0 * ldc + n0) = pack_bf2(h0, h1);
                *reinterpret_cast<uint32_t*>(Clo + czb + m0 * ldc + n0) = pack_bf2(l0, l1);
                bsplit(cc[2], h0, l0); bsplit(cc[3], h1, l1);
                *reinterpret_cast<uint32_t*>(Chi + czb + m1 * ldc + n0) = pack_bf2(h0, h1);
                *reinterpret_cast<uint32_t*>(Clo + czb + m1 * ldc + n0) = pack_bf2(l0, l1);
            } else {
#pragma unroll
                for (int half = 0; half < 2; half++) {
                    long long m = half ? m1 : m0;
                    int bb = (int)(m >> 10), ss = (int)(m & 1023);
                    long long base = (long long)bb * DMODEL * TSEQ + ss;
#pragma unroll
                    for (int j = 0; j < 2; j++) {
                        __nv_bfloat16 hh, ll;
                        bsplit(cc[half * 2 + j], hh, ll);
                        Chi[base + (long long)(n0 + j) * TSEQ] = hh;
                        Clo[base + (long long)(n0 + j) * TSEQ] = ll;
                    }
                }
            }
        }
    }
}

// ===================== attention score pass (single pass; stores exp splits) =====================
// grid (TSEQ/128, NH, BSZ), 256 threads; 3-stage pipeline; stage = (i, ch, kh) of Q/K tiles.
#define AS_RSPART 196608
#define AS_RS128  198656
#define AS_SMEM   199168

__global__ __launch_bounds__(256) void attn_score(
    const __nv_bfloat16* __restrict__ Qh, const __nv_bfloat16* __restrict__ Ql,
    const __nv_bfloat16* __restrict__ Kh, const __nv_bfloat16* __restrict__ Kl,
    __nv_bfloat16* __restrict__ PTh, __nv_bfloat16* __restrict__ PTl,
    float* __restrict__ inv_out)
{
    extern __shared__ __align__(1024) char sm[];
    int tid = threadIdx.x, wid = tid >> 5, l = tid & 31;
    int wm = wid >> 2, wn = wid & 3;
    uint32_t sb = smem_u32(sm);
    float* rspart = reinterpret_cast<float*>(sm + AS_RSPART);  // 128 x 4
    float* rs128  = reinterpret_cast<float*>(sm + AS_RS128);   // 128

    int b = blockIdx.z, h = blockIdx.y, t0 = blockIdx.x * 128;
    const float SC = 0.08838834764831845f;   // 1/sqrt(128)
    int g = l >> 2, q2 = (l & 3) * 2;

    if (tid < 128) rs128[tid] = 0.f;
    __syncthreads();

    float c[4][4][4];
#pragma unroll
    for (int a = 0; a < 4; a++)
#pragma unroll
        for (int b2 = 0; b2 < 4; b2++)
#pragma unroll
            for (int d = 0; d < 4; d++) c[a][b2][d] = 0.f;

    const int S = 128;   // 8i x 8ch x 2kh
    auto stage_load = [&](int s) {
        int kh = s & 1, t = s >> 1, i = t >> 3, ch = t & 7;
        size_t qb = ((size_t)(i * BSZ + b) * TSEQ + t0) * DMODEL + h * HD + kh * 64;
        size_t kb = ((size_t)(i * BSZ + b) * TSEQ + ch * 128) * DMODEL + h * HD + kh * 64;
        uint32_t bo = sb + (s % 3) * 65536;
        tile_cp(bo,         Qh + qb, DMODEL, tid);
        tile_cp(bo + 16384, Ql + qb, DMODEL, tid);
        tile_cp(bo + 32768, Kh + kb, DMODEL, tid);
        tile_cp(bo + 49152, Kl + kb, DMODEL, tid);
        CP_COMMIT();
    };
    stage_load(0);
    stage_load(1);

    size_t bh_base = ((size_t)(b * NH + h)) << 20;   // *TSEQ*TSEQ

    for (int s = 0; s < S; s++) {
        if (s + 2 < S) { stage_load(s + 2); CP_WAIT2(); }
        else if (s + 1 < S) CP_WAIT1();
        else CP_WAIT0();
        __syncthreads();
        uint32_t bo = sb + (s % 3) * 65536;
#pragma unroll
        for (int s16 = 0; s16 < 4; s16++) {
            int kb = s16 * 16;
            uint32_t bh[4][2], bl[4][2];
#pragma unroll
            for (int nt = 0; nt < 4; nt++) {
                uint32_t ad = swz(bo + 32768, wn * 32 + nt * 8 + (l & 7),
                                  (kb + ((l >> 3) & 1) * 8) * 2);
                ldm2(bh[nt], ad);
                ldm2(bl[nt], ad + 16384);
            }
#pragma unroll
            for (int mt = 0; mt < 4; mt++) {
                uint32_t ah[4], al[4];
                uint32_t aa = swz(bo, wm * 64 + mt * 16 + (l & 15),
                                  (kb + ((l >> 4) & 1) * 8) * 2);
                ldm4(ah, aa);
                ldm4(al, aa + 16384);
#pragma unroll
                for (int nt = 0; nt < 4; nt++) {
                    mma_bf(c[mt][nt], ah, bh[nt]);
                    mma_bf(c[mt][nt], ah, bl[nt]);
                    mma_bf(c[mt][nt], al, bh[nt]);
                }
            }
        }
        int kh = s & 1, t = s >> 1, i = t >> 3, ch = t & 7;
        if (kh == 1) {
            size_t rowbase = (size_t)i * PT_PLANE + bh_base + ((size_t)t0 << 10);
            float ps[8];
#pragma unroll
            for (int mt = 0; mt < 4; mt++) {
                int r0 = wm * 64 + mt * 16 + g, r1 = r0 + 8;
                float s0 = 0.f, s1 = 0.f;
#pragma unroll
                for (int nt = 0; nt < 4; nt++) {
                    int col = ch * 128 + wn * 32 + nt * 8 + q2;
                    float e0 = __expf(c[mt][nt][0] * SC);
                    float e1 = __expf(c[mt][nt][1] * SC);
                    float e2 = __expf(c[mt][nt][2] * SC);
                    float e3 = __expf(c[mt][nt][3] * SC);
                    s0 += e0 + e1; s1 += e2 + e3;
                    __nv_bfloat16 hh0, ll0, hh1, ll1;
                    bsplit(e0, hh0, ll0); bsplit(e1, hh1, ll1);
                    *reinterpret_cast<uint32_t*>(PTh + rowbase + ((size_t)r0 << 10) + col) = pack_bf2(hh0, hh1);
                    *reinterpret_cast<uint32_t*>(PTl + rowbase + ((size_t)r0 << 10) + col) = pack_bf2(ll0, ll1);
                    bsplit(e2, hh0, ll0); bsplit(e3, hh1, ll1);
                    *reinterpret_cast<uint32_t*>(PTh + rowbase + ((size_t)r1 << 10) + col) = pack_bf2(hh0, hh1);
                    *reinterpret_cast<uint32_t*>(PTl + rowbase + ((size_t)r1 << 10) + col) = pack_bf2(ll0, ll1);
                }
                ps[2 * mt] = s0; ps[2 * mt + 1] = s1;
            }
#pragma unroll
            for (int off = 1; off <= 2; off <<= 1)
#pragma unroll
                for (int k = 0; k < 8; k++)
                    ps[k] += __shfl_xor_sync(0xffffffffu, ps[k], off);
            if ((l & 3) == 0) {
#pragma unroll
                for (int mt = 0; mt < 4; mt++) {
                    int r0 = wm * 64 + mt * 16 + g;
                    rspart[r0 * 4 + wn] = ps[2 * mt];
                    rspart[(r0 + 8) * 4 + wn] = ps[2 * mt + 1];
                }
            }
            __syncthreads();
            if (tid < 128) {
                rs128[tid] += rspart[tid * 4] + rspart[tid * 4 + 1] +
                              rspart[tid * 4 + 2] + rspart[tid * 4 + 3];
                if (ch == 7) {
                    inv_out[i * (BSZ * NH * TSEQ) + (b * NH + h) * TSEQ + t0 + tid] =
                        0.125f / rs128[tid];
                    rs128[tid] = 0.f;
                }
            }
#pragma unroll
            for (int a = 0; a < 4; a++)
#pragma unroll
                for (int b2 = 0; b2 < 4; b2++)
#pragma unroll
                    for (int d = 0; d < 4; d++) c[a][b2][d] = 0.f;
        }
        __syncthreads();
    }
}

// ===================== normalize + mean over i =====================
// grid: BSZ*NH*TSEQ CTAs (one per attention row), 256 threads x 4 s-elements.
__global__ __launch_bounds__(256) void attn_norm(
    const __nv_bfloat16* __restrict__ PTh, const __nv_bfloat16* __restrict__ PTl,
    const float* __restrict__ inv,
    float* __restrict__ attn_out, __nv_bfloat16* __restrict__ Ph, __nv_bfloat16* __restrict__ Pl)
{
    int r = blockIdx.x;              // (b*NH+h)*TSEQ + t
    int s4 = threadIdx.x * 4;
    size_t rowoff = ((size_t)r << 10);
    float acc0 = 0.f, acc1 = 0.f, acc2 = 0.f, acc3 = 0.f;
#pragma unroll
    for (int i = 0; i < 8; i++) {
        float iv = inv[i * (BSZ * NH * TSEQ) + r];
        size_t off = (size_t)i * PT_PLANE + rowoff + s4;
        uint2 hv = *reinterpret_cast<const uint2*>(PTh + off);
        uint2 lv = *reinterpret_cast<const uint2*>(PTl + off);
        __nv_bfloat162 h01 = *reinterpret_cast<__nv_bfloat162*>(&hv.x);
        __nv_bfloat162 h23 = *reinterpret_cast<__nv_bfloat162*>(&hv.y);
        __nv_bfloat162 l01 = *reinterpret_cast<__nv_bfloat162*>(&lv.x);
        __nv_bfloat162 l23 = *reinterpret_cast<__nv_bfloat162*>(&lv.y);
        acc0 += (__bfloat162float(h01.x) + __bfloat162float(l01.x)) * iv;
        acc1 += (__bfloat162float(h01.y) + __bfloat162float(l01.y)) * iv;
        acc2 += (__bfloat162float(h23.x) + __bfloat162float(l23.x)) * iv;
        acc3 += (__bfloat162float(h23.y) + __bfloat162float(l23.y)) * iv;
    }
    *reinterpret_cast<float4*>(attn_out + rowoff + s4) = make_float4(acc0, acc1, acc2, acc3);
    __nv_bfloat16 h0, l0, h1, l1, h2, l2, h3, l3;
    bsplit(acc0, h0, l0); bsplit(acc1, h1, l1);
    bsplit(acc2, h2, l2); bsplit(acc3, h3, l3);
    *reinterpret_cast<uint2*>(Ph + rowoff + s4) = make_uint2(pack_bf2(h0, h1), pack_bf2(h2, h3));
    *reinterpret_cast<uint2*>(Pl + rowoff + s4) = make_uint2(pack_bf2(l0, l1), pack_bf2(l2, l3));
}

// ===================== host =====================
extern "C" void kernel_launch(void* const* d_in, const int* in_sizes, int n_in,
                              void* d_out, int out_size) {
    (void)in_sizes; (void)n_in; (void)out_size;
    const float* query = (const float*)d_in[0];
    const float* key   = (const float*)d_in[1];
    const float* value = (const float*)d_in[2];
    const float* Wq    = (const float*)d_in[3];
    const float* Wk    = (const float*)d_in[4];
    const float* Wv    = (const float*)d_in[5];
    const float* Wo    = (const float*)d_in[6];
    float* out = (float*)d_out;
    float* out_attn = out + (size_t)BT * DMODEL;

    __nv_bfloat16* S;
    cudaGetSymbolAddress((void**)&S, g_bf);
    float* pInv;
    cudaGetSymbolAddress((void**)&pInv, g_inv);
#define AT(o) (S + (size_t)(o))

    cudaFuncSetAttribute(gemm_bx3, cudaFuncAttributeMaxDynamicSharedMemorySize, G_SMEM);
    cudaFuncSetAttribute(attn_score, cudaFuncAttributeMaxDynamicSharedMemorySize, AS_SMEM);

    // splits
    cvt_k<<<2048, 256>>>(query, AT(O_QRH), AT(O_QRL), 524288);
    cvt_k<<<2048, 256>>>(key,   AT(O_KYH), AT(O_KYL), 524288);
    cvt_k<<<2048, 256>>>(value, AT(O_VAH), AT(O_VAL), 524288);
    cvt_k<<<8192, 256>>>(Wq,    AT(O_WQH), AT(O_WQL), 2097152);
    cvt_k<<<8192, 256>>>(Wk,    AT(O_WKH), AT(O_WKL), 2097152);
    cvt_k<<<1024, 256>>>(Wv,    AT(O_WVH), AT(O_WVL), 262144);
    cvt_k<<<1024, 256>>>(Wo,    AT(O_WOH), AT(O_WOL), 262144);

    dim3 blk(256);
    // Q_i = query @ Wq[i]^T (bf16-split out), K_i = key @ Wk[i]^T
    gemm_bx3<<<dim3(8, 16, 8), blk, G_SMEM>>>(
        AT(O_QRH), AT(O_QRL), AT(O_WQH), AT(O_WQL), nullptr, AT(O_QH), AT(O_QL),
        16, DMODEL, DMODEL, DMODEL, 1,
        0LL, 0LL, (long long)DMODEL * DMODEL, 0LL, (long long)BT * DMODEL, 0LL, 1);
    gemm_bx3<<<dim3(8, 16, 8), blk, G_SMEM>>>(
        AT(O_KYH), AT(O_KYL), AT(O_WKH), AT(O_WKL), nullptr, AT(O_KH), AT(O_KL),
        16, DMODEL, DMODEL, DMODEL, 1,
        0LL, 0LL, (long long)DMODEL * DMODEL, 0LL, (long long)BT * DMODEL, 0LL, 1);
    // Vt = (value @ Wv^T)^T (transposed split out)
    gemm_bx3<<<dim3(8, 16, 1), blk, G_SMEM>>>(
        AT(O_VAH), AT(O_VAL), AT(O_WVH), AT(O_WVL), nullptr, AT(O_VTH), AT(O_VTL),
        16, DMODEL, DMODEL, DMODEL, 1, 0LL, 0LL, 0LL, 0LL, 0LL, 0LL, 2);

    // scores: single pass, store exp splits + row normalizers
    attn_score<<<dim3(TSEQ / 128, NH, BSZ), blk, AS_SMEM>>>(
        AT(O_QH), AT(O_QL), AT(O_KH), AT(O_KL), AT(O_PTH), AT(O_PTL), pInv);

    // normalize + mean over i -> attention output + split P
    attn_norm<<<BSZ * NH * TSEQ, blk>>>(
        AT(O_PTH), AT(O_PTL), pInv, out_attn, AT(O_PH), AT(O_PL));

    // head[b,t,h*128+e] = sum_s P[b,h,t,s] * Vt[b,h*128+e,s] (split out)
    gemm_bx3<<<dim3(1, 8, 16), blk, G_SMEM>>>(
        AT(O_PH), AT(O_PL), AT(O_VTH), AT(O_VTL), nullptr, AT(O_HH), AT(O_HL),
        16, TSEQ, TSEQ, DMODEL, 8,
        (long long)NH * TSEQ * TSEQ, (long long)TSEQ * TSEQ,
        (long long)DMODEL * TSEQ, (long long)HD * TSEQ,
        (long long)TSEQ * DMODEL, (long long)HD, 1);

    // outputs = head @ Wo^T (fp32)
    gemm_bx3<<<dim3(8, 16, 1), blk, G_SMEM>>>(
        AT(O_HH), AT(O_HL), AT(O_WOH), AT(O_WOL), out, nullptr, nullptr,
        16, DMODEL, DMODEL, DMODEL, 1, 0LL, 0LL, 0LL, 0LL, 0LL, 0LL, 0);
}

// round 6
// speedup vs baseline: 4.6761x; 1.1191x over previous
#include <cuda_runtime.h>
#include <cuda_bf16.h>
#include <cuda_fp16.h>
#include <cstdint>

#define BSZ 2
#define TSEQ 1024
#define DMODEL 1024
#define NH 8
#define HD 128
#define BT (BSZ * TSEQ)

// ===================== low-level helpers (sm_80+ instructions only) =====================
__device__ __forceinline__ uint32_t smem_u32(const void* p) {
    uint32_t a;
    asm("{ .reg .u64 t; cvta.to.shared.u64 t, %1; cvt.u32.u64 %0, t; }" : "=r"(a) : "l"(p));
    return a;
}
#define CP_ASYNC16(sm_addr, gptr) \
    asm volatile("cp.async.cg.shared.global [%0], [%1], 16;" :: "r"(sm_addr), "l"(gptr))
#define CP_COMMIT() asm volatile("cp.async.commit_group;")
#define CP_WAIT0()  asm volatile("cp.async.wait_group 0;")
#define CP_WAIT1()  asm volatile("cp.async.wait_group 1;")

__device__ __forceinline__ void ldm4(uint32_t* r, uint32_t a) {
    asm volatile("ldmatrix.sync.aligned.m8n8.x4.shared.b16 {%0,%1,%2,%3}, [%4];"
                 : "=r"(r[0]), "=r"(r[1]), "=r"(r[2]), "=r"(r[3]) : "r"(a));
}
__device__ __forceinline__ void ldm2(uint32_t* r, uint32_t a) {
    asm volatile("ldmatrix.sync.aligned.m8n8.x2.shared.b16 {%0,%1}, [%2];"
                 : "=r"(r[0]), "=r"(r[1]) : "r"(a));
}
__device__ __forceinline__ void mma_bf(float* c, const uint32_t* a, const uint32_t* b) {
    asm volatile(
        "mma.sync.aligned.m16n8k16.row.col.f32.bf16.bf16.f32 "
        "{%0,%1,%2,%3}, {%4,%5,%6,%7}, {%8,%9}, {%0,%1,%2,%3};"
        : "+f"(c[0]), "+f"(c[1]), "+f"(c[2]), "+f"(c[3])
        : "r"(a[0]), "r"(a[1]), "r"(a[2]), "r"(a[3]), "r"(b[0]), "r"(b[1]));
}
__device__ __forceinline__ void mma_fp(float* c, const uint32_t* a, const uint32_t* b) {
    asm volatile(
        "mma.sync.aligned.m16n8k16.row.col.f32.f16.f16.f32 "
        "{%0,%1,%2,%3}, {%4,%5,%6,%7}, {%8,%9}, {%0,%1,%2,%3};"
        : "+f"(c[0]), "+f"(c[1]), "+f"(c[2]), "+f"(c[3])
        : "r"(a[0]), "r"(a[1]), "r"(a[2]), "r"(a[3]), "r"(b[0]), "r"(b[1]));
}
template <int MMAT>
__device__ __forceinline__ void mma_any(float* c, const uint32_t* a, const uint32_t* b) {
    if constexpr (MMAT == 0) mma_bf(c, a, b);
    else mma_fp(c, a, b);
}
// tiles are 128 rows x 64 elems of b16 (128B rows) with 16B-granular XOR swizzle
__device__ __forceinline__ uint32_t swz(uint32_t base, int row, int kbytes) {
    uint32_t bo = (uint32_t)(row * 128 + kbytes);
    return base + (bo ^ ((bo >> 3) & 0x70));
}
__device__ __forceinline__ void tile_cp(uint32_t sdst, const __nv_bfloat16* __restrict__ src,
                                        int rstride, int tid) {
#pragma unroll
    for (int it = 0; it < 4; it++) {
        int f = tid + it * 256;
        int row = f >> 3, c8 = (f & 7) << 3;
        uint32_t bo = (uint32_t)(row * 128 + c8 * 2);
        uint32_t sw = bo ^ ((bo >> 3) & 0x70);
        CP_ASYNC16(sdst + sw, src + (size_t)row * rstride + c8);
    }
}
__device__ __forceinline__ void bsplit(float v, __nv_bfloat16& h, __nv_bfloat16& l) {
    h = __float2bfloat16(v);
    l = __float2bfloat16(v - __bfloat162float(h));
}
__device__ __forceinline__ uint32_t pack_bf2(__nv_bfloat16 a, __nv_bfloat16 b) {
    __nv_bfloat162 t; t.x = a; t.y = b;
    return *reinterpret_cast<uint32_t*>(&t);
}
__device__ __forceinline__ uint32_t pack_h2(__half a, __half b) {
    __half2 t; t.x = a; t.y = b;
    return *reinterpret_cast<uint32_t*>(&t);
}
__device__ __forceinline__ void hsplit(float v, __half& h, __half& l) {
    h = __float2half_rn(v);
    l = __float2half_rn(v - __half2float(h));
}

// ===================== scratch offsets (2-byte elements) =====================
#define MEG 1048576LL
#define O_QRH (0LL)
#define O_QRL (2 * MEG)
#define O_KYH (4 * MEG)
#define O_KYL (6 * MEG)
#define O_VAH (8 * MEG)
#define O_VAL (10 * MEG)
#define O_WQH (12 * MEG)
#define O_WQL (20 * MEG)
#define O_WKH (28 * MEG)
#define O_WKL (36 * MEG)
#define O_WVH (44 * MEG)
#define O_WVL (45 * MEG)
#define O_WOH (46 * MEG)
#define O_WOL (47 * MEG)
#define O_QH  (48 * MEG)
#define O_QL  (64 * MEG)
#define O_KH  (80 * MEG)
#define O_KL  (96 * MEG)
#define O_VTH (112 * MEG)            // fp16 split Vt
#define O_VTL (114 * MEG)
#define O_PH  (116 * MEG)            // fp16 split P
#define O_PL  (132 * MEG)
#define O_HH  (148 * MEG)            // bf16 split head
#define O_HL  (150 * MEG)
#define O_PT  (152 * MEG)            // fp16 unnormalized exp: 8 planes x 16M
#define SCRATCH_ELEMS (280 * MEG)
__device__ __nv_bfloat16 g_bf[SCRATCH_ELEMS];
__device__ float g_inv[8 * BSZ * NH * TSEQ];   // 0.125/rowsum per (i, b, h, t)

#define PT_PLANE 16777216LL          // BSZ*NH*TSEQ*TSEQ per i

// ===================== fp32 -> bf16 hi/lo split (8 elems/thread) =====================
__global__ __launch_bounds__(256) void cvt_k(const float* __restrict__ x,
                                             __nv_bfloat16* __restrict__ hi,
                                             __nv_bfloat16* __restrict__ lo, int n8) {
    int i = blockIdx.x * 256 + threadIdx.x;
    if (i >= n8) return;
    float4 v0 = reinterpret_cast<const float4*>(x)[2 * i];
    float4 v1 = reinterpret_cast<const float4*>(x)[2 * i + 1];
    __nv_bfloat16 h[8], l[8];
    bsplit(v0.x, h[0], l[0]); bsplit(v0.y, h[1], l[1]);
    bsplit(v0.z, h[2], l[2]); bsplit(v0.w, h[3], l[3]);
    bsplit(v1.x, h[4], l[4]); bsplit(v1.y, h[5], l[5]);
    bsplit(v1.z, h[6], l[6]); bsplit(v1.w, h[7], l[7]);
    reinterpret_cast<uint4*>(hi)[i] = make_uint4(pack_bf2(h[0], h[1]), pack_bf2(h[2], h[3]),
                                                 pack_bf2(h[4], h[5]), pack_bf2(h[6], h[7]));
    reinterpret_cast<uint4*>(lo)[i] = make_uint4(pack_bf2(l[0], l[1]), pack_bf2(l[2], l[3]),
                                                 pack_bf2(l[4], l[5]), pack_bf2(l[6], l[7]));
}

// ===================== generic bx3 GEMM: C = A @ B^T =====================
// MMAT: 0 = bf16 MMA, 1 = fp16 MMA. A: M x K, B: N x K (hi/lo pairs).
// modes: 0 = fp32 C; 1 = bf16-split C; 2 = fp16-split transposed C (Vt[b][n][s])
#define G_SMEM 196608   // 3 stages x 64KB

template <int MMAT>
__global__ __launch_bounds__(256) void gemm_bx3(
    const __nv_bfloat16* __restrict__ Ahi, const __nv_bfloat16* __restrict__ Alo,
    const __nv_bfloat16* __restrict__ Bhi, const __nv_bfloat16* __restrict__ Blo,
    float* __restrict__ Cf, __nv_bfloat16* __restrict__ Chi, __nv_bfloat16* __restrict__ Clo,
    int kchunks, int lda, int ldb, int ldc, int zdiv,
    long long sA1, long long sA2, long long sB1, long long sB2,
    long long sC1, long long sC2, int mode)
{
    extern __shared__ __align__(1024) char sm[];
    int tid = threadIdx.x, wid = tid >> 5, l = tid & 31;
    int wm = wid >> 2, wn = wid & 3;
    uint32_t sb = smem_u32(sm);

    long long zq = blockIdx.z / zdiv, zr = blockIdx.z % zdiv;
    const __nv_bfloat16* A0 = Ahi + zq * sA1 + zr * sA2 + (long long)blockIdx.y * 128 * lda;
    const __nv_bfloat16* A1 = Alo + zq * sA1 + zr * sA2 + (long long)blockIdx.y * 128 * lda;
    const __nv_bfloat16* B0 = Bhi + zq * sB1 + zr * sB2 + (long long)blockIdx.x * 128 * ldb;
    const __nv_bfloat16* B1 = Blo + zq * sB1 + zr * sB2 + (long long)blockIdx.x * 128 * ldb;

    float c[4][4][4];
#pragma unroll
    for (int a = 0; a < 4; a++)
#pragma unroll
        for (int b2 = 0; b2 < 4; b2++)
#pragma unroll
            for (int d = 0; d < 4; d++) c[a][b2][d] = 0.f;

    auto load_chunk = [&](int ck) {
        uint32_t bo = sb + (ck % 3) * 65536;
        tile_cp(bo,         A0 + ck * 64, lda, tid);
        tile_cp(bo + 16384, A1 + ck * 64, lda, tid);
        tile_cp(bo + 32768, B0 + ck * 64, ldb, tid);
        tile_cp(bo + 49152, B1 + ck * 64, ldb, tid);
        CP_COMMIT();
    };
    load_chunk(0);
    if (kchunks > 1) load_chunk(1);

    for (int ck = 0; ck < kchunks; ck++) {
        if (ck + 1 < kchunks) CP_WAIT1();
        else CP_WAIT0();
        __syncthreads();
        if (ck + 2 < kchunks) load_chunk(ck + 2);
        uint32_t bo = sb + (ck % 3) * 65536;
#pragma unroll
        for (int s16 = 0; s16 < 4; s16++) {
            int kb = s16 * 16;
            uint32_t bh[4][2], bl[4][2];
#pragma unroll
            for (int nt = 0; nt < 4; nt++) {
                uint32_t ad = swz(bo + 32768, wn * 32 + nt * 8 + (l & 7),
                                  (kb + ((l >> 3) & 1) * 8) * 2);
                ldm2(bh[nt], ad);
                ldm2(bl[nt], ad + 16384);
            }
#pragma unroll
            for (int mt = 0; mt < 4; mt++) {
                uint32_t ah[4], al[4];
                uint32_t aa = swz(bo, wm * 64 + mt * 16 + (l & 15),
                                  (kb + ((l >> 4) & 1) * 8) * 2);
                ldm4(ah, aa);
                ldm4(al, aa + 16384);
#pragma unroll
                for (int nt = 0; nt < 4; nt++) {
                    mma_any<MMAT>(c[mt][nt], ah, bh[nt]);
                    mma_any<MMAT>(c[mt][nt], ah, bl[nt]);
                    mma_any<MMAT>(c[mt][nt], al, bh[nt]);
                }
            }
        }
    }

    // epilogue
    int g = l >> 2, q2 = (l & 3) * 2;
    long long czb = zq * sC1 + zr * sC2;
#pragma unroll
    for (int mt = 0; mt < 4; mt++) {
        long long m0 = (long long)blockIdx.y * 128 + wm * 64 + mt * 16 + g;
        long long m1 = m0 + 8;
#pragma unroll
        for (int nt = 0; nt < 4; nt++) {
            int n0 = blockIdx.x * 128 + wn * 32 + nt * 8 + q2;
            float* cc = c[mt][nt];
            if (mode == 0) {
                *reinterpret_cast<float2*>(Cf + czb + m0 * ldc + n0) = make_float2(cc[0], cc[1]);
                *reinterpret_cast<float2*>(Cf + czb + m1 * ldc + n0) = make_float2(cc[2], cc[3]);
            } else if (mode == 1) {
                __nv_bfloat16 h0, l0, h1, l1;
                bsplit(cc[0], h0, l0); bsplit(cc[1], h1, l1);
                *reinterpret_cast<uint32_t*>(Chi + czb + m0 * ldc + n0) = pack_bf2(h0, h1);
                *reinterpret_cast<uint32_t*>(Clo + czb + m0 * ldc + n0) = pack_bf2(l0, l1);
                bsplit(cc[2], h0, l0); bsplit(cc[3], h1, l1);
                *reinterpret_cast<uint32_t*>(Chi + czb + m1 * ldc + n0) = pack_bf2(h0, h1);
                *reinterpret_cast<uint32_t*>(Clo + czb + m1 * ldc + n0) = pack_bf2(l0, l1);
            } else {
                // fp16-split transposed store: C[b][n][s], m -> (b, s)
                __half* ChiH = reinterpret_cast<__half*>(Chi);
                __half* CloH = reinterpret_cast<__half*>(Clo);
#pragma unroll
                for (int half = 0; half < 2; half++) {
                    long long m = half ? m1 : m0;
                    int bb = (int)(m >> 10), ss = (int)(m & 1023);
                    long long base = (long long)bb * DMODEL * TSEQ + ss;
#pragma unroll
                    for (int j = 0; j < 2; j++) {
                        __half hh, ll;
                        hsplit(cc[half * 2 + j], hh, ll);
                        ChiH[base + (long long)(n0 + j) * TSEQ] = hh;
                        CloH[base + (long long)(n0 + j) * TSEQ] = ll;
                    }
                }
            }
        }
    }
}

// ===================== attention score pass (stores fp16 exp + normalizers) =====================
#define AS_RSPART 196608
#define AS_RS128  198656
#define AS_SMEM   199168

__global__ __launch_bounds__(256) void attn_score(
    const __nv_bfloat16* __restrict__ Qh, const __nv_bfloat16* __restrict__ Ql,
    const __nv_bfloat16* __restrict__ Kh, const __nv_bfloat16* __restrict__ Kl,
    __half* __restrict__ PT, float* __restrict__ inv_out)
{
    extern __shared__ __align__(1024) char sm[];
    int tid = threadIdx.x, wid = tid >> 5, l = tid & 31;
    int wm = wid >> 2, wn = wid & 3;
    uint32_t sb = smem_u32(sm);
    float* rspart = reinterpret_cast<float*>(sm + AS_RSPART);  // 128 x 4
    float* rs128  = reinterpret_cast<float*>(sm + AS_RS128);   // 128

    int b = blockIdx.z, h = blockIdx.y, t0 = blockIdx.x * 128;
    const float SC = 0.08838834764831845f;   // 1/sqrt(128)
    int g = l >> 2, q2 = (l & 3) * 2;

    if (tid < 128) rs128[tid] = 0.f;
    __syncthreads();

    float c[4][4][4];
#pragma unroll
    for (int a = 0; a < 4; a++)
#pragma unroll
        for (int b2 = 0; b2 < 4; b2++)
#pragma unroll
            for (int d = 0; d < 4; d++) c[a][b2][d] = 0.f;

    const int S = 128;   // 8i x 8ch x 2kh
    auto stage_load = [&](int s) {
        int kh = s & 1, t = s >> 1, i = t >> 3, ch = t & 7;
        size_t qb = ((size_t)(i * BSZ + b) * TSEQ + t0) * DMODEL + h * HD + kh * 64;
        size_t kb = ((size_t)(i * BSZ + b) * TSEQ + ch * 128) * DMODEL + h * HD + kh * 64;
        uint32_t bo = sb + (s % 3) * 65536;
        tile_cp(bo,         Qh + qb, DMODEL, tid);
        tile_cp(bo + 16384, Ql + qb, DMODEL, tid);
        tile_cp(bo + 32768, Kh + kb, DMODEL, tid);
        tile_cp(bo + 49152, Kl + kb, DMODEL, tid);
        CP_COMMIT();
    };
    stage_load(0);
    stage_load(1);

    size_t bh_base = ((size_t)(b * NH + h)) << 20;   // *TSEQ*TSEQ

    for (int s = 0; s < S; s++) {
        if (s + 1 < S) CP_WAIT1();
        else CP_WAIT0();
        __syncthreads();
        if (s + 2 < S) stage_load(s + 2);
        uint32_t bo = sb + (s % 3) * 65536;
#pragma unroll
        for (int s16 = 0; s16 < 4; s16++) {
            int kb = s16 * 16;
            uint32_t bh[4][2], bl[4][2];
#pragma unroll
            for (int nt = 0; nt < 4; nt++) {
                uint32_t ad = swz(bo + 32768, wn * 32 + nt * 8 + (l & 7),
                                  (kb + ((l >> 3) & 1) * 8) * 2);
                ldm2(bh[nt], ad);
                ldm2(bl[nt], ad + 16384);
            }
#pragma unroll
            for (int mt = 0; mt < 4; mt++) {
                uint32_t ah[4], al[4];
                uint32_t aa = swz(bo, wm * 64 + mt * 16 + (l & 15),
                                  (kb + ((l >> 4) & 1) * 8) * 2);
                ldm4(ah, aa);
                ldm4(al, aa + 16384);
#pragma unroll
                for (int nt = 0; nt < 4; nt++) {
                    mma_bf(c[mt][nt], ah, bh[nt]);
                    mma_bf(c[mt][nt], ah, bl[nt]);
                    mma_bf(c[mt][nt], al, bh[nt]);
                }
            }
        }
        int kh = s & 1, t = s >> 1, i = t >> 3, ch = t & 7;
        if (kh == 1) {
            size_t rowbase = (size_t)i * PT_PLANE + bh_base + ((size_t)t0 << 10);
            float ps[8];
#pragma unroll
            for (int mt = 0; mt < 4; mt++) {
                int r0 = wm * 64 + mt * 16 + g, r1 = r0 + 8;
                float s0 = 0.f, s1 = 0.f;
#pragma unroll
                for (int nt = 0; nt < 4; nt++) {
                    int col = ch * 128 + wn * 32 + nt * 8 + q2;
                    float e0 = __expf(c[mt][nt][0] * SC);
                    float e1 = __expf(c[mt][nt][1] * SC);
                    float e2 = __expf(c[mt][nt][2] * SC);
                    float e3 = __expf(c[mt][nt][3] * SC);
                    s0 += e0 + e1; s1 += e2 + e3;
                    *reinterpret_cast<uint32_t*>(PT + rowbase + ((size_t)r0 << 10) + col) =
                        pack_h2(__float2half_rn(e0), __float2half_rn(e1));
                    *reinterpret_cast<uint32_t*>(PT + rowbase + ((size_t)r1 << 10) + col) =
                        pack_h2(__float2half_rn(e2), __float2half_rn(e3));
                }
                ps[2 * mt] = s0; ps[2 * mt + 1] = s1;
            }
#pragma unroll
            for (int off = 1; off <= 2; off <<= 1)
#pragma unroll
                for (int k = 0; k < 8; k++)
                    ps[k] += __shfl_xor_sync(0xffffffffu, ps[k], off);
            if ((l & 3) == 0) {
#pragma unroll
                for (int mt = 0; mt < 4; mt++) {
                    int r0 = wm * 64 + mt * 16 + g;
                    rspart[r0 * 4 + wn] = ps[2 * mt];
                    rspart[(r0 + 8) * 4 + wn] = ps[2 * mt + 1];
                }
            }
            __syncthreads();
            if (tid < 128) {
                rs128[tid] += rspart[tid * 4] + rspart[tid * 4 + 1] +
                              rspart[tid * 4 + 2] + rspart[tid * 4 + 3];
                if (ch == 7) {
                    inv_out[i * (BSZ * NH * TSEQ) + (b * NH + h) * TSEQ + t0 + tid] =
                        0.125f / rs128[tid];
                    rs128[tid] = 0.f;
                }
            }
#pragma unroll
            for (int a = 0; a < 4; a++)
#pragma unroll
                for (int b2 = 0; b2 < 4; b2++)
#pragma unroll
                    for (int d = 0; d < 4; d++) c[a][b2][d] = 0.f;
        }
    }
}

// ===================== normalize + mean over i =====================
__global__ __launch_bounds__(256) void attn_norm(
    const __half* __restrict__ PT, const float* __restrict__ inv,
    float* __restrict__ attn_out, __half* __restrict__ Ph, __half* __restrict__ Pl)
{
    int r = blockIdx.x;              // (b*NH+h)*TSEQ + t
    int s4 = threadIdx.x * 4;
    size_t rowoff = ((size_t)r << 10);
    float acc0 = 0.f, acc1 = 0.f, acc2 = 0.f, acc3 = 0.f;
#pragma unroll
    for (int i = 0; i < 8; i++) {
        float iv = inv[i * (BSZ * NH * TSEQ) + r];
        size_t off = (size_t)i * PT_PLANE + rowoff + s4;
        uint2 hv = *reinterpret_cast<const uint2*>(PT + off);
        __half2 h01 = *reinterpret_cast<__half2*>(&hv.x);
        __half2 h23 = *reinterpret_cast<__half2*>(&hv.y);
        acc0 += __half2float(h01.x) * iv;
        acc1 += __half2float(h01.y) * iv;
        acc2 += __half2float(h23.x) * iv;
        acc3 += __half2float(h23.y) * iv;
    }
    *reinterpret_cast<float4*>(attn_out + rowoff + s4) = make_float4(acc0, acc1, acc2, acc3);
    __half h0, l0, h1, l1, h2, l2, h3, l3;
    hsplit(acc0, h0, l0); hsplit(acc1, h1, l1);
    hsplit(acc2, h2, l2); hsplit(acc3, h3, l3);
    *reinterpret_cast<uint2*>(Ph + rowoff + s4) = make_uint2(pack_h2(h0, h1), pack_h2(h2, h3));
    *reinterpret_cast<uint2*>(Pl + rowoff + s4) = make_uint2(pack_h2(l0, l1), pack_h2(l2, l3));
}

// ===================== host =====================
extern "C" void kernel_launch(void* const* d_in, const int* in_sizes, int n_in,
                              void* d_out, int out_size) {
    (void)in_sizes; (void)n_in; (void)out_size;
    const float* query = (const float*)d_in[0];
    const float* key   = (const float*)d_in[1];
    const float* value = (const float*)d_in[2];
    const float* Wq    = (const float*)d_in[3];
    const float* Wk    = (const float*)d_in[4];
    const float* Wv    = (const float*)d_in[5];
    const float* Wo    = (const float*)d_in[6];
    float* out = (float*)d_out;
    float* out_attn = out + (size_t)BT * DMODEL;

    __nv_bfloat16* S;
    cudaGetSymbolAddress((void**)&S, g_bf);
    float* pInv;
    cudaGetSymbolAddress((void**)&pInv, g_inv);
#define AT(o) (S + (size_t)(o))
#define ATH(o) (reinterpret_cast<__half*>(S + (size_t)(o)))

    cudaFuncSetAttribute(gemm_bx3<0>, cudaFuncAttributeMaxDynamicSharedMemorySize, G_SMEM);
    cudaFuncSetAttribute(gemm_bx3<1>, cudaFuncAttributeMaxDynamicSharedMemorySize, G_SMEM);
    cudaFuncSetAttribute(attn_score, cudaFuncAttributeMaxDynamicSharedMemorySize, AS_SMEM);

    // splits (8 elems/thread)
    cvt_k<<<1024, 256>>>(query, AT(O_QRH), AT(O_QRL), 262144);
    cvt_k<<<1024, 256>>>(key,   AT(O_KYH), AT(O_KYL), 262144);
    cvt_k<<<1024, 256>>>(value, AT(O_VAH), AT(O_VAL), 262144);
    cvt_k<<<4096, 256>>>(Wq,    AT(O_WQH), AT(O_WQL), 1048576);
    cvt_k<<<4096, 256>>>(Wk,    AT(O_WKH), AT(O_WKL), 1048576);
    cvt_k<<<512, 256>>>(Wv,     AT(O_WVH), AT(O_WVL), 131072);
    cvt_k<<<512, 256>>>(Wo,     AT(O_WOH), AT(O_WOL), 131072);

    dim3 blk(256);
    // Q_i = query @ Wq[i]^T (bf16-split out), K_i = key @ Wk[i]^T
    gemm_bx3<0><<<dim3(8, 16, 8), blk, G_SMEM>>>(
        AT(O_QRH), AT(O_QRL), AT(O_WQH), AT(O_WQL), nullptr, AT(O_QH), AT(O_QL),
        16, DMODEL, DMODEL, DMODEL, 1,
        0LL, 0LL, (long long)DMODEL * DMODEL, 0LL, (long long)BT * DMODEL, 0LL, 1);
    gemm_bx3<0><<<dim3(8, 16, 8), blk, G_SMEM>>>(
        AT(O_KYH), AT(O_KYL), AT(O_WKH), AT(O_WKL), nullptr, AT(O_KH), AT(O_KL),
        16, DMODEL, DMODEL, DMODEL, 1,
        0LL, 0LL, (long long)DMODEL * DMODEL, 0LL, (long long)BT * DMODEL, 0LL, 1);
    // Vt = (value @ Wv^T)^T (fp16-split transposed out)
    gemm_bx3<0><<<dim3(8, 16, 1), blk, G_SMEM>>>(
        AT(O_VAH), AT(O_VAL), AT(O_WVH), AT(O_WVL), nullptr, AT(O_VTH), AT(O_VTL),
        16, DMODEL, DMODEL, DMODEL, 1, 0LL, 0LL, 0LL, 0LL, 0LL, 0LL, 2);

    // scores: single pass, store fp16 exp + row normalizers
    attn_score<<<dim3(TSEQ / 128, NH, BSZ), blk, AS_SMEM>>>(
        AT(O_QH), AT(O_QL), AT(O_KH), AT(O_KL), ATH(O_PT), pInv);

    // normalize + mean over i -> attention output + fp16-split P
    attn_norm<<<BSZ * NH * TSEQ, blk>>>(
        ATH(O_PT), pInv, out_attn, ATH(O_PH), ATH(O_PL));

    // head[b,t,h*128+e] = sum_s P[b,h,t,s] * Vt[b,h*128+e,s] (fp16 MMA, bf16-split out)
    gemm_bx3<1><<<dim3(1, 8, 16), blk, G_SMEM>>>(
        AT(O_PH), AT(O_PL), AT(O_VTH), AT(O_VTL), nullptr, AT(O_HH), AT(O_HL),
        16, TSEQ, TSEQ, DMODEL, 8,
        (long long)NH * TSEQ * TSEQ, (long long)TSEQ * TSEQ,
        (long long)DMODEL * TSEQ, (long long)HD * TSEQ,
        (long long)TSEQ * DMODEL, (long long)HD, 1);

    // outputs = head @ Wo^T (fp32)
    gemm_bx3<0><<<dim3(8, 16, 1), blk, G_SMEM>>>(
        AT(O_HH), AT(O_HL), AT(O_WOH), AT(O_WOL), out, nullptr, nullptr,
        16, DMODEL, DMODEL, DMODEL, 1, 0LL, 0LL, 0LL, 0LL, 0LL, 0LL, 0);
}